// round 11
// baseline (speedup 1.0000x reference)
#include <cuda_runtime.h>
#include <cuda_fp16.h>
#include <math.h>

#define S_LEN 2048
#define D_DIM 1024
#define NHEAD 16
#define DH 64
#define POSLEN 512
#define C2P_ELEMS (NHEAD * S_LEN * POSLEN)

typedef unsigned long long u64;

__device__ float g_q[S_LEN * D_DIM];
__device__ float g_k[S_LEN * D_DIM];
__device__ float g_v[S_LEN * D_DIM];
__device__ float g_pk[POSLEN * D_DIM];
__device__ float g_pq[POSLEN * D_DIM];
__device__ __half g_c2p_h[C2P_ELEMS];
__device__ __half g_p2c_h[C2P_ELEMS];

// ---------------- packed fp32x2 helpers (Blackwell FFMA2 path) ----------------
__device__ __forceinline__ void dfma2(u64& d, u64 a, u64 b) {
    asm("fma.rn.f32x2 %0, %1, %2, %0;" : "+l"(d) : "l"(a), "l"(b));
}
__device__ __forceinline__ void dmul2(u64& d, u64 a) {
    asm("mul.rn.f32x2 %0, %0, %1;" : "+l"(d) : "l"(a));
}
__device__ __forceinline__ u64 bc2(float x) {
    u64 r; asm("mov.b64 %0, {%1, %1};" : "=l"(r) : "f"(x)); return r;
}
__device__ __forceinline__ u64 pk2(float x, float y) {
    u64 r; asm("mov.b64 %0, {%1, %2};" : "=l"(r) : "f"(x), "f"(y)); return r;
}
__device__ __forceinline__ void unp2(u64 v, float& x, float& y) {
    asm("mov.b64 {%0, %1}, %2;" : "=f"(x), "=f"(y) : "l"(v));
}

// ================= projection GEMM: C_z = A(Mx1024) @ W_z(1024x1024) + b_z =================
__global__ __launch_bounds__(256) void gemm_proj(
    const float* __restrict__ A,
    const float* __restrict__ W0, const float* __restrict__ W1, const float* __restrict__ W2,
    const float* __restrict__ b0, const float* __restrict__ b1, const float* __restrict__ b2,
    float* __restrict__ C0, float* __restrict__ C1, float* __restrict__ C2)
{
    const float* W; const float* bias; float* C;
    if (blockIdx.z == 0)      { W = W0; bias = b0; C = C0; }
    else if (blockIdx.z == 1) { W = W1; bias = b1; C = C1; }
    else                      { W = W2; bias = b2; C = C2; }

    __shared__ float As[16][132];
    __shared__ float Bs[16][132];

    const int tid = threadIdx.x;
    const int tr = tid >> 4, tc = tid & 15;
    const int m0 = blockIdx.y * 128, n0 = blockIdx.x * 128;

    u64 acc2[4][8] = {};   // row-pair x col

    for (int k0 = 0; k0 < 1024; k0 += 16) {
        #pragma unroll
        for (int u = 0; u < 2; u++) {
            int idx = tid + u * 256;
            int r = idx >> 2, c4 = idx & 3;
            float4 av = *(const float4*)(A + (size_t)(m0 + r) * 1024 + k0 + c4 * 4);
            As[c4 * 4 + 0][r] = av.x; As[c4 * 4 + 1][r] = av.y;
            As[c4 * 4 + 2][r] = av.z; As[c4 * 4 + 3][r] = av.w;
        }
        #pragma unroll
        for (int u = 0; u < 2; u++) {
            int idx = tid + u * 256;
            int r = idx >> 5, c4 = idx & 31;
            float4 bv = *(const float4*)(W + (size_t)(k0 + r) * 1024 + n0 + c4 * 4);
            *(float4*)(&Bs[r][c4 * 4]) = bv;
        }
        __syncthreads();
        #pragma unroll
        for (int kk = 0; kk < 16; kk++) {
            ulonglong2 a01 = *(const ulonglong2*)(&As[kk][tr * 8]);
            ulonglong2 a23 = *(const ulonglong2*)(&As[kk][tr * 8 + 4]);
            u64 ap[4] = {a01.x, a01.y, a23.x, a23.y};
            float b[8];
            *(float4*)(b)     = *(const float4*)(&Bs[kk][tc * 8]);
            *(float4*)(b + 4) = *(const float4*)(&Bs[kk][tc * 8 + 4]);
            #pragma unroll
            for (int j = 0; j < 8; j++) {
                u64 bb = bc2(b[j]);
                #pragma unroll
                for (int ip = 0; ip < 4; ip++) dfma2(acc2[ip][j], ap[ip], bb);
            }
        }
        __syncthreads();
    }

    #pragma unroll
    for (int ip = 0; ip < 4; ip++) {
        float r0[8], r1[8];
        #pragma unroll
        for (int j = 0; j < 8; j++) {
            unp2(acc2[ip][j], r0[j], r1[j]);
            float bj = bias[n0 + tc * 8 + j];
            r0[j] += bj; r1[j] += bj;
        }
        int ma = m0 + tr * 8 + 2 * ip;
        *(float4*)(C + (size_t)ma * 1024 + n0 + tc * 8)           = *(float4*)(&r0[0]);
        *(float4*)(C + (size_t)ma * 1024 + n0 + tc * 8 + 4)       = *(float4*)(&r0[4]);
        *(float4*)(C + (size_t)(ma + 1) * 1024 + n0 + tc * 8)     = *(float4*)(&r1[0]);
        *(float4*)(C + (size_t)(ma + 1) * 1024 + n0 + tc * 8 + 4) = *(float4*)(&r1[4]);
    }
}

// ================= per-head NT GEMM -> fp16 table =================
__global__ __launch_bounds__(256) void gemm_rel(
    const float* __restrict__ A, const float* __restrict__ B, __half* __restrict__ C,
    int M, int N)
{
    __shared__ float As[16][132];
    __shared__ float Bs[16][132];

    const int tid = threadIdx.x;
    const int tr = tid >> 4, tc = tid & 15;
    const int h = blockIdx.z;
    const int hb = h * DH;
    const int m0 = blockIdx.y * 128, n0 = blockIdx.x * 128;

    u64 acc2[4][8] = {};

    for (int k0 = 0; k0 < 64; k0 += 16) {
        #pragma unroll
        for (int u = 0; u < 2; u++) {
            int idx = tid + u * 256;
            int r = idx >> 2, c4 = idx & 3;
            float4 av = *(const float4*)(A + (size_t)(m0 + r) * 1024 + hb + k0 + c4 * 4);
            As[c4 * 4 + 0][r] = av.x; As[c4 * 4 + 1][r] = av.y;
            As[c4 * 4 + 2][r] = av.z; As[c4 * 4 + 3][r] = av.w;
        }
        #pragma unroll
        for (int u = 0; u < 2; u++) {
            int idx = tid + u * 256;
            int r = idx >> 2, c4 = idx & 3;
            float4 bv = *(const float4*)(B + (size_t)(n0 + r) * 1024 + hb + k0 + c4 * 4);
            Bs[c4 * 4 + 0][r] = bv.x; Bs[c4 * 4 + 1][r] = bv.y;
            Bs[c4 * 4 + 2][r] = bv.z; Bs[c4 * 4 + 3][r] = bv.w;
        }
        __syncthreads();
        #pragma unroll
        for (int kk = 0; kk < 16; kk++) {
            ulonglong2 a01 = *(const ulonglong2*)(&As[kk][tr * 8]);
            ulonglong2 a23 = *(const ulonglong2*)(&As[kk][tr * 8 + 4]);
            u64 ap[4] = {a01.x, a01.y, a23.x, a23.y};
            float b[8];
            *(float4*)(b)     = *(const float4*)(&Bs[kk][tc * 8]);
            *(float4*)(b + 4) = *(const float4*)(&Bs[kk][tc * 8 + 4]);
            #pragma unroll
            for (int j = 0; j < 8; j++) {
                u64 bb = bc2(b[j]);
                #pragma unroll
                for (int ip = 0; ip < 4; ip++) dfma2(acc2[ip][j], ap[ip], bb);
            }
        }
        __syncthreads();
    }

    __half* Ch = C + (size_t)h * M * N;
    #pragma unroll
    for (int ip = 0; ip < 4; ip++) {
        float r0[8], r1[8];
        #pragma unroll
        for (int j = 0; j < 8; j++) unp2(acc2[ip][j], r0[j], r1[j]);
        int ma = m0 + tr * 8 + 2 * ip;
        __half2 h0[4], h1[4];
        #pragma unroll
        for (int p = 0; p < 4; p++) {
            h0[p] = __floats2half2_rn(r0[2 * p], r0[2 * p + 1]);
            h1[p] = __floats2half2_rn(r1[2 * p], r1[2 * p + 1]);
        }
        *(int4*)(Ch + (size_t)ma * N + n0 + tc * 8)       = *(int4*)h0;
        *(int4*)(Ch + (size_t)(ma + 1) * N + n0 + tc * 8) = *(int4*)h1;
    }
}

// ================= fused flash attention =================
// 64x64 tiles, 256 threads (16x16), 4x4 micro-tile (row-pair packed FFMA2),
// double-buffered K/V with register-staged prefetch, hoisted gathers.
#define ATT_SMEM_FLOATS (64*68 + 2*64*68 + 64*68 + 2*64*64)   // qsT, ksT[2], ssT, vs[2]

__device__ __forceinline__ float rmax16(float v) {
    #pragma unroll
    for (int off = 8; off; off >>= 1)
        v = fmaxf(v, __shfl_xor_sync(0xffffffffu, v, off));
    return v;
}
__device__ __forceinline__ float rsum16(float v) {
    #pragma unroll
    for (int off = 8; off; off >>= 1)
        v += __shfl_xor_sync(0xffffffffu, v, off);
    return v;
}

__global__ __launch_bounds__(256, 2) void attn2(
    const float* __restrict__ Q, const float* __restrict__ Km,
    const float* __restrict__ V, const __half* __restrict__ c2p,
    const __half* __restrict__ p2c, const int* __restrict__ ids,
    const int* __restrict__ ids_t, float* __restrict__ out)
{
    extern __shared__ float sm[];
    float* qsT = sm;                       // [64 kk][68]
    float* ksT = qsT + 64 * 68;            // 2 x [64 kk][68]
    float* ssT = ksT + 2 * 64 * 68;        // [64 col][68]
    float* vs  = ssT + 64 * 68;            // 2 x [64 j][64]

    const int h  = blockIdx.y;
    const int s0 = blockIdx.x * 64;
    const int hb = h * DH;
    const int tid = threadIdx.x;
    const int ty = tid >> 4, tx = tid & 15;

    const float inv_scale = 0.07216878364870322f;  // 1/sqrt(64*3)

    // Q tile transposed + K/V tile 0 into buffer 0
    #pragma unroll
    for (int u = 0; u < 4; u++) {
        int idx = tid + u * 256;
        int c4 = idx >> 6, r = idx & 63;
        float4 qv = *(const float4*)(Q + (size_t)(s0 + r) * 1024 + hb + c4 * 4);
        qsT[(c4 * 4 + 0) * 68 + r] = qv.x; qsT[(c4 * 4 + 1) * 68 + r] = qv.y;
        qsT[(c4 * 4 + 2) * 68 + r] = qv.z; qsT[(c4 * 4 + 3) * 68 + r] = qv.w;
        float4 kv = *(const float4*)(Km + (size_t)r * 1024 + hb + c4 * 4);
        ksT[(c4 * 4 + 0) * 68 + r] = kv.x; ksT[(c4 * 4 + 1) * 68 + r] = kv.y;
        ksT[(c4 * 4 + 2) * 68 + r] = kv.z; ksT[(c4 * 4 + 3) * 68 + r] = kv.w;
        int rv = idx >> 4, cv = idx & 15;
        float4 vv = *(const float4*)(V + (size_t)rv * 1024 + hb + cv * 4);
        *(float4*)(&vs[rv * 64 + cv * 4]) = vv;
    }

    float m_run[4], l_run[4];
    #pragma unroll
    for (int i = 0; i < 4; i++) { m_run[i] = -INFINITY; l_run[i] = 0.f; }
    u64 o2[2][4] = {};
    __syncthreads();

    for (int t0 = 0; t0 < S_LEN; t0 += 64) {
        const int buf = (t0 >> 6) & 1;
        float* ksb = ksT + buf * 64 * 68;
        float* vsb = vs + buf * 64 * 64;

        // ---- index loads (L2/DRAM) ----
        int4 ivr[4], ivc[4];
        #pragma unroll
        for (int i = 0; i < 4; i++)
            ivr[i] = *(const int4*)(ids + (((size_t)h * S_LEN + s0 + ty * 4 + i) << 11) + t0 + tx * 4);
        #pragma unroll
        for (int jj = 0; jj < 4; jj++)
            ivc[jj] = *(const int4*)(ids_t + (((size_t)h * S_LEN + t0 + tx * 4 + jj) << 11) + s0 + ty * 4);

        // ---- prefetch next K/V tile into registers (latency spans whole iter) ----
        const int nt = (t0 + 64 < S_LEN) ? t0 + 64 : t0;
        float4 kr[4], vr[4];
        #pragma unroll
        for (int u = 0; u < 4; u++) {
            int idx = tid + u * 256;
            int c4 = idx >> 6, r = idx & 63;
            kr[u] = *(const float4*)(Km + (size_t)(nt + r) * 1024 + hb + c4 * 4);
            int rv = idx >> 4, cv = idx & 15;
            vr[u] = *(const float4*)(V + (size_t)(nt + rv) * 1024 + hb + cv * 4);
        }

        // ---- random table gathers (fp16, L2-resident) ----
        __half gc[4][4], gp[4][4];
        #pragma unroll
        for (int i = 0; i < 4; i++) {
            gc[i][0] = c2p[ivr[i].x]; gc[i][1] = c2p[ivr[i].y];
            gc[i][2] = c2p[ivr[i].z]; gc[i][3] = c2p[ivr[i].w];
        }
        #pragma unroll
        for (int jj = 0; jj < 4; jj++) {
            gp[0][jj] = p2c[ivc[jj].x]; gp[1][jj] = p2c[ivc[jj].y];
            gp[2][jj] = p2c[ivc[jj].z]; gp[3][jj] = p2c[ivc[jj].w];
        }

        // ---- QK^T, row-pair packed ----
        u64 acc2[2][4] = {};
        #pragma unroll 8
        for (int kk = 0; kk < 64; kk++) {
            ulonglong2 ap = *(const ulonglong2*)(qsT + kk * 68 + ty * 4);
            float b[4];
            *(float4*)b = *(const float4*)(ksb + kk * 68 + tx * 4);
            #pragma unroll
            for (int jj = 0; jj < 4; jj++) {
                u64 bb = bc2(b[jj]);
                dfma2(acc2[0][jj], ap.x, bb);
                dfma2(acc2[1][jj], ap.y, bb);
            }
        }

        // ---- unpack, add biases, scale ----
        float s[4][4];
        #pragma unroll
        for (int ip = 0; ip < 2; ip++)
            #pragma unroll
            for (int jj = 0; jj < 4; jj++)
                unp2(acc2[ip][jj], s[2 * ip][jj], s[2 * ip + 1][jj]);
        #pragma unroll
        for (int i = 0; i < 4; i++)
            #pragma unroll
            for (int jj = 0; jj < 4; jj++)
                s[i][jj] = (s[i][jj] + __half2float(gc[i][jj]) + __half2float(gp[i][jj])) * inv_scale;

        // ---- online softmax via 16-lane shuffles ----
        float corr[4];
        #pragma unroll
        for (int i = 0; i < 4; i++) {
            float mt = fmaxf(fmaxf(s[i][0], s[i][1]), fmaxf(s[i][2], s[i][3]));
            mt = rmax16(mt);
            float mn = fmaxf(m_run[i], mt);
            corr[i] = __expf(m_run[i] - mn);
            m_run[i] = mn;
            float ls = 0.f;
            #pragma unroll
            for (int jj = 0; jj < 4; jj++) {
                s[i][jj] = __expf(s[i][jj] - mn);
                ls += s[i][jj];
            }
            ls = rsum16(ls);
            l_run[i] = l_run[i] * corr[i] + ls;
        }
        u64 c01 = pk2(corr[0], corr[1]), c23 = pk2(corr[2], corr[3]);
        #pragma unroll
        for (int jj = 0; jj < 4; jj++) { dmul2(o2[0][jj], c01); dmul2(o2[1][jj], c23); }

        // ---- exchange probs (col-major) ----
        #pragma unroll
        for (int jj = 0; jj < 4; jj++) {
            float4 s4;
            s4.x = s[0][jj]; s4.y = s[1][jj]; s4.z = s[2][jj]; s4.w = s[3][jj];
            *(float4*)(ssT + (tx * 4 + jj) * 68 + ty * 4) = s4;
        }
        __syncthreads();

        // ---- PV, row-pair packed ----
        #pragma unroll 8
        for (int j = 0; j < 64; j++) {
            ulonglong2 pp = *(const ulonglong2*)(ssT + j * 68 + ty * 4);
            float vv[4];
            *(float4*)vv = *(const float4*)(vsb + j * 64 + tx * 4);
            #pragma unroll
            for (int jj = 0; jj < 4; jj++) {
                u64 bb = bc2(vv[jj]);
                dfma2(o2[0][jj], pp.x, bb);
                dfma2(o2[1][jj], pp.y, bb);
            }
        }

        // ---- commit prefetched K/V into the other buffer ----
        float* ksn = ksT + (buf ^ 1) * 64 * 68;
        float* vsn = vs + (buf ^ 1) * 64 * 64;
        #pragma unroll
        for (int u = 0; u < 4; u++) {
            int idx = tid + u * 256;
            int c4 = idx >> 6, r = idx & 63;
            ksn[(c4 * 4 + 0) * 68 + r] = kr[u].x; ksn[(c4 * 4 + 1) * 68 + r] = kr[u].y;
            ksn[(c4 * 4 + 2) * 68 + r] = kr[u].z; ksn[(c4 * 4 + 3) * 68 + r] = kr[u].w;
            int rv = idx >> 4, cv = idx & 15;
            *(float4*)(&vsn[rv * 64 + cv * 4]) = vr[u];
        }
        __syncthreads();
    }

    #pragma unroll
    for (int ip = 0; ip < 2; ip++) {
        float r0[4], r1[4];
        #pragma unroll
        for (int jj = 0; jj < 4; jj++) unp2(o2[ip][jj], r0[jj], r1[jj]);
        float inv0 = 1.f / l_run[2 * ip], inv1 = 1.f / l_run[2 * ip + 1];
        float4 ov0, ov1;
        ov0.x = r0[0] * inv0; ov0.y = r0[1] * inv0; ov0.z = r0[2] * inv0; ov0.w = r0[3] * inv0;
        ov1.x = r1[0] * inv1; ov1.y = r1[1] * inv1; ov1.z = r1[2] * inv1; ov1.w = r1[3] * inv1;
        int ra = s0 + ty * 4 + 2 * ip;
        *(float4*)(out + (size_t)ra * 1024 + hb + tx * 4)       = ov0;
        *(float4*)(out + (size_t)(ra + 1) * 1024 + hb + tx * 4) = ov1;
    }
}

// ================= host launcher =================
extern "C" void kernel_launch(void* const* d_in, const int* in_sizes, int n_in,
                              void* d_out, int out_size)
{
    const float* hidden = (const float*)d_in[0];
    const float* rel    = (const float*)d_in[1];
    const float* Wq     = (const float*)d_in[2];
    const float* bq     = (const float*)d_in[3];
    const float* Wk     = (const float*)d_in[4];
    const float* bk     = (const float*)d_in[5];
    const float* Wv     = (const float*)d_in[6];
    const float* bv     = (const float*)d_in[7];
    const int*   ids    = (const int*)d_in[8];
    const int*   ids_t  = (const int*)d_in[9];
    float* out = (float*)d_out;

    void *pq, *pk, *pv, *ppk, *ppq, *pc2p, *pp2c;
    cudaGetSymbolAddress(&pq, g_q);
    cudaGetSymbolAddress(&pk, g_k);
    cudaGetSymbolAddress(&pv, g_v);
    cudaGetSymbolAddress(&ppk, g_pk);
    cudaGetSymbolAddress(&ppq, g_pq);
    cudaGetSymbolAddress(&pc2p, g_c2p_h);
    cudaGetSymbolAddress(&pp2c, g_p2c_h);
    float* q = (float*)pq;  float* k = (float*)pk;  float* v = (float*)pv;
    float* posk = (float*)ppk; float* posq = (float*)ppq;
    __half* c2p = (__half*)pc2p; __half* p2c = (__half*)pp2c;

    static int smem_set = 0;
    if (!smem_set) {
        cudaFuncSetAttribute(attn2, cudaFuncAttributeMaxDynamicSharedMemorySize,
                             ATT_SMEM_FLOATS * 4);
        smem_set = 1;
    }

    dim3 gq(1024 / 128, S_LEN / 128, 3);
    gemm_proj<<<gq, 256>>>(hidden, Wq, Wk, Wv, bq, bk, bv, q, k, v);

    dim3 gp(1024 / 128, POSLEN / 128, 2);
    gemm_proj<<<gp, 256>>>(rel, Wk, Wq, Wq, bk, bq, bq, posk, posq, posq);

    dim3 gc(POSLEN / 128, S_LEN / 128, NHEAD);
    gemm_rel<<<gc, 256>>>(q, posk, c2p, S_LEN, POSLEN);
    gemm_rel<<<gc, 256>>>(k, posq, p2c, S_LEN, POSLEN);

    dim3 ga(S_LEN / 64, NHEAD);
    attn2<<<ga, 256, ATT_SMEM_FLOATS * 4>>>(q, k, v, c2p, p2c, ids, ids_t, out);
}

// round 12
// speedup vs baseline: 2.2752x; 2.2752x over previous
#include <cuda_runtime.h>
#include <cuda_fp16.h>
#include <math.h>
#include <stdint.h>

#define S_LEN 2048
#define D_DIM 1024
#define NHEAD 16
#define DH 64
#define POSLEN 512
#define C2P_ELEMS (NHEAD * S_LEN * POSLEN)

__device__ float g_q[S_LEN * D_DIM];
__device__ float g_k[S_LEN * D_DIM];
__device__ float g_v[S_LEN * D_DIM];
__device__ float g_pk[POSLEN * D_DIM];
__device__ float g_pq[POSLEN * D_DIM];
__device__ __half g_c2p_h[C2P_ELEMS];
__device__ __half g_p2c_h[C2P_ELEMS];

// ---------------- tf32 helpers ----------------
__device__ __forceinline__ uint32_t f2tf32(float f) {
    uint32_t r;
    asm("cvt.rna.tf32.f32 %0, %1;" : "=r"(r) : "f"(f));
    return r;
}
__device__ __forceinline__ void mma_tf32(
    float& d0, float& d1, float& d2, float& d3,
    uint32_t a0, uint32_t a1, uint32_t a2, uint32_t a3,
    uint32_t b0, uint32_t b1)
{
    asm("mma.sync.aligned.m16n8k8.row.col.f32.tf32.tf32.f32 "
        "{%0,%1,%2,%3}, {%4,%5,%6,%7}, {%8,%9}, {%0,%1,%2,%3};"
        : "+f"(d0), "+f"(d1), "+f"(d2), "+f"(d3)
        : "r"(a0), "r"(a1), "r"(a2), "r"(a3), "r"(b0), "r"(b1));
}
__device__ __forceinline__ uint4 cvt4(float4 v) {
    uint4 r;
    r.x = f2tf32(v.x); r.y = f2tf32(v.y); r.z = f2tf32(v.z); r.w = f2tf32(v.w);
    return r;
}

// ================= tf32 tensor-core projection GEMM =================
// C_z = A(Mx1024) @ W_z(1024x1024) + b_z ; 128x128 tile, 8 warps (2x4), warp 64x32.
__global__ __launch_bounds__(256) void gemm_proj_tc(
    const float* __restrict__ A,
    const float* __restrict__ W0, const float* __restrict__ W1, const float* __restrict__ W2,
    const float* __restrict__ b0, const float* __restrict__ b1, const float* __restrict__ b2,
    float* __restrict__ C0, float* __restrict__ C1, float* __restrict__ C2)
{
    const float* W; const float* bias; float* C;
    if (blockIdx.z == 0)      { W = W0; bias = b0; C = C0; }
    else if (blockIdx.z == 1) { W = W1; bias = b1; C = C1; }
    else                      { W = W2; bias = b2; C = C2; }

    __shared__ uint32_t As[128 * 36];   // [m][k] k-tile 32, pad 36
    __shared__ uint32_t Bs[32 * 136];   // [k][n] pad 136

    const int tid = threadIdx.x;
    const int w = tid >> 5, lane = tid & 31;
    const int g = lane >> 2, tg = lane & 3;
    const int wm = (w >> 2) * 64, wn = (w & 3) * 32;
    const int m0 = blockIdx.y * 128, n0 = blockIdx.x * 128;

    float d[4][4][4] = {};

    for (int k0 = 0; k0 < 1024; k0 += 32) {
        #pragma unroll
        for (int u = 0; u < 4; u++) {
            int idx = tid + u * 256;             // A: 1024 float4
            int r = idx >> 3, c4 = idx & 7;
            float4 av = *(const float4*)(A + (size_t)(m0 + r) * 1024 + k0 + c4 * 4);
            *(uint4*)(As + r * 36 + c4 * 4) = cvt4(av);
        }
        #pragma unroll
        for (int u = 0; u < 4; u++) {
            int idx = tid + u * 256;             // B: 1024 float4
            int r = idx >> 5, c4 = idx & 31;
            float4 bv = *(const float4*)(W + (size_t)(k0 + r) * 1024 + n0 + c4 * 4);
            *(uint4*)(Bs + r * 136 + c4 * 4) = cvt4(bv);
        }
        __syncthreads();

        #pragma unroll
        for (int ks = 0; ks < 4; ks++) {
            uint32_t af[4][4];
            #pragma unroll
            for (int mt = 0; mt < 4; mt++) {
                int row = wm + mt * 16 + g;
                af[mt][0] = As[row * 36 + ks * 8 + tg];
                af[mt][1] = As[(row + 8) * 36 + ks * 8 + tg];
                af[mt][2] = As[row * 36 + ks * 8 + tg + 4];
                af[mt][3] = As[(row + 8) * 36 + ks * 8 + tg + 4];
            }
            uint32_t bf[4][2];
            #pragma unroll
            for (int nt = 0; nt < 4; nt++) {
                int col = wn + nt * 8 + g;
                bf[nt][0] = Bs[(ks * 8 + tg) * 136 + col];
                bf[nt][1] = Bs[(ks * 8 + tg + 4) * 136 + col];
            }
            #pragma unroll
            for (int mt = 0; mt < 4; mt++)
                #pragma unroll
                for (int nt = 0; nt < 4; nt++)
                    mma_tf32(d[mt][nt][0], d[mt][nt][1], d[mt][nt][2], d[mt][nt][3],
                             af[mt][0], af[mt][1], af[mt][2], af[mt][3],
                             bf[nt][0], bf[nt][1]);
        }
        __syncthreads();
    }

    #pragma unroll
    for (int mt = 0; mt < 4; mt++) {
        int row = m0 + wm + mt * 16 + g;
        #pragma unroll
        for (int nt = 0; nt < 4; nt++) {
            int col = n0 + wn + nt * 8 + tg * 2;
            float bb0 = bias[col], bb1 = bias[col + 1];
            float2 v0 = make_float2(d[mt][nt][0] + bb0, d[mt][nt][1] + bb1);
            float2 v1 = make_float2(d[mt][nt][2] + bb0, d[mt][nt][3] + bb1);
            *(float2*)(C + (size_t)row * 1024 + col)       = v0;
            *(float2*)(C + (size_t)(row + 8) * 1024 + col) = v1;
        }
    }
}

// ================= tf32 tensor-core per-head NT GEMM -> fp16 table =================
// C[h] = A_h(Mx64) @ B_h^T(Nx64); B rows are col-major K x N for mma row.col.
__global__ __launch_bounds__(256) void gemm_rel_tc(
    const float* __restrict__ A, const float* __restrict__ B, __half* __restrict__ C,
    int M, int N)
{
    __shared__ uint32_t As[128 * 36];   // [m][k]
    __shared__ uint32_t Bs[128 * 36];   // [n][k]

    const int tid = threadIdx.x;
    const int w = tid >> 5, lane = tid & 31;
    const int g = lane >> 2, tg = lane & 3;
    const int wm = (w >> 2) * 64, wn = (w & 3) * 32;
    const int h = blockIdx.z;
    const int hb = h * DH;
    const int m0 = blockIdx.y * 128, n0 = blockIdx.x * 128;

    float d[4][4][4] = {};

    for (int k0 = 0; k0 < 64; k0 += 32) {
        #pragma unroll
        for (int u = 0; u < 4; u++) {
            int idx = tid + u * 256;
            int r = idx >> 3, c4 = idx & 7;
            float4 av = *(const float4*)(A + (size_t)(m0 + r) * 1024 + hb + k0 + c4 * 4);
            *(uint4*)(As + r * 36 + c4 * 4) = cvt4(av);
        }
        #pragma unroll
        for (int u = 0; u < 4; u++) {
            int idx = tid + u * 256;
            int r = idx >> 3, c4 = idx & 7;
            float4 bv = *(const float4*)(B + (size_t)(n0 + r) * 1024 + hb + k0 + c4 * 4);
            *(uint4*)(Bs + r * 36 + c4 * 4) = cvt4(bv);
        }
        __syncthreads();

        #pragma unroll
        for (int ks = 0; ks < 4; ks++) {
            uint32_t af[4][4];
            #pragma unroll
            for (int mt = 0; mt < 4; mt++) {
                int row = wm + mt * 16 + g;
                af[mt][0] = As[row * 36 + ks * 8 + tg];
                af[mt][1] = As[(row + 8) * 36 + ks * 8 + tg];
                af[mt][2] = As[row * 36 + ks * 8 + tg + 4];
                af[mt][3] = As[(row + 8) * 36 + ks * 8 + tg + 4];
            }
            uint32_t bf[4][2];
            #pragma unroll
            for (int nt = 0; nt < 4; nt++) {
                int col = wn + nt * 8 + g;     // n-row of Bs
                bf[nt][0] = Bs[col * 36 + ks * 8 + tg];
                bf[nt][1] = Bs[col * 36 + ks * 8 + tg + 4];
            }
            #pragma unroll
            for (int mt = 0; mt < 4; mt++)
                #pragma unroll
                for (int nt = 0; nt < 4; nt++)
                    mma_tf32(d[mt][nt][0], d[mt][nt][1], d[mt][nt][2], d[mt][nt][3],
                             af[mt][0], af[mt][1], af[mt][2], af[mt][3],
                             bf[nt][0], bf[nt][1]);
        }
        __syncthreads();
    }

    __half* Ch = C + (size_t)h * M * N;
    #pragma unroll
    for (int mt = 0; mt < 4; mt++) {
        int row = m0 + wm + mt * 16 + g;
        #pragma unroll
        for (int nt = 0; nt < 4; nt++) {
            int col = n0 + wn + nt * 8 + tg * 2;
            *(__half2*)(Ch + (size_t)row * N + col) =
                __floats2half2_rn(d[mt][nt][0], d[mt][nt][1]);
            *(__half2*)(Ch + (size_t)(row + 8) * N + col) =
                __floats2half2_rn(d[mt][nt][2], d[mt][nt][3]);
        }
    }
}

// ================= fused flash attention (round-6 known-good version) =================
#define ATT_SMEM_FLOATS (3 * 64 * 68 + 64 * 64)

__device__ __forceinline__ float rmax16(float v) {
    #pragma unroll
    for (int off = 8; off; off >>= 1)
        v = fmaxf(v, __shfl_xor_sync(0xffffffffu, v, off));
    return v;
}
__device__ __forceinline__ float rsum16(float v) {
    #pragma unroll
    for (int off = 8; off; off >>= 1)
        v += __shfl_xor_sync(0xffffffffu, v, off);
    return v;
}

__global__ __launch_bounds__(256, 2) void attn2(
    const float* __restrict__ Q, const float* __restrict__ Km,
    const float* __restrict__ V, const __half* __restrict__ c2p,
    const __half* __restrict__ p2c, const int* __restrict__ ids,
    const int* __restrict__ ids_t, float* __restrict__ out)
{
    extern __shared__ float sm[];
    float* qsT = sm;               // [64 kk][68]
    float* ksT = qsT + 64 * 68;    // [64 kk][68]
    float* ssT = ksT + 64 * 68;    // [64 col][68] probs, col-major
    float* vs  = ssT + 64 * 68;    // [64 j][64 dim]

    const int h  = blockIdx.y;
    const int s0 = blockIdx.x * 64;
    const int hb = h * DH;
    const int tid = threadIdx.x;
    const int ty = tid >> 4, tx = tid & 15;

    const float inv_scale = 0.07216878364870322f;  // 1/sqrt(64*3)

    #pragma unroll
    for (int u = 0; u < 4; u++) {
        int idx = tid + u * 256;
        int c4 = idx >> 6, r = idx & 63;
        float4 qv = *(const float4*)(Q + (size_t)(s0 + r) * 1024 + hb + c4 * 4);
        qsT[(c4 * 4 + 0) * 68 + r] = qv.x; qsT[(c4 * 4 + 1) * 68 + r] = qv.y;
        qsT[(c4 * 4 + 2) * 68 + r] = qv.z; qsT[(c4 * 4 + 3) * 68 + r] = qv.w;
    }

    float m_run[4], l_run[4];
    #pragma unroll
    for (int i = 0; i < 4; i++) { m_run[i] = -INFINITY; l_run[i] = 0.f; }
    float o[4][4] = {};

    for (int t0 = 0; t0 < S_LEN; t0 += 64) {
        // ---- bias index loads + gathers first (hidden under K/V load + QK) ----
        float bc[4][4], bp[4][4];
        {
            int4 ivr[4], ivc[4];
            #pragma unroll
            for (int i = 0; i < 4; i++)
                ivr[i] = *(const int4*)(ids + (((size_t)h * S_LEN + s0 + ty * 4 + i) << 11) + t0 + tx * 4);
            #pragma unroll
            for (int jj = 0; jj < 4; jj++)
                ivc[jj] = *(const int4*)(ids_t + (((size_t)h * S_LEN + t0 + tx * 4 + jj) << 11) + s0 + ty * 4);
            #pragma unroll
            for (int i = 0; i < 4; i++) {
                bc[i][0] = __half2float(c2p[ivr[i].x]);
                bc[i][1] = __half2float(c2p[ivr[i].y]);
                bc[i][2] = __half2float(c2p[ivr[i].z]);
                bc[i][3] = __half2float(c2p[ivr[i].w]);
            }
            #pragma unroll
            for (int jj = 0; jj < 4; jj++) {
                bp[0][jj] = __half2float(p2c[ivc[jj].x]);
                bp[1][jj] = __half2float(p2c[ivc[jj].y]);
                bp[2][jj] = __half2float(p2c[ivc[jj].z]);
                bp[3][jj] = __half2float(p2c[ivc[jj].w]);
            }
        }

        #pragma unroll
        for (int u = 0; u < 4; u++) {
            int idx = tid + u * 256;
            int c4 = idx >> 6, r = idx & 63;
            float4 kv = *(const float4*)(Km + (size_t)(t0 + r) * 1024 + hb + c4 * 4);
            ksT[(c4 * 4 + 0) * 68 + r] = kv.x; ksT[(c4 * 4 + 1) * 68 + r] = kv.y;
            ksT[(c4 * 4 + 2) * 68 + r] = kv.z; ksT[(c4 * 4 + 3) * 68 + r] = kv.w;
        }
        #pragma unroll
        for (int u = 0; u < 4; u++) {
            int idx = tid + u * 256;
            int r = idx >> 4, c4 = idx & 15;
            float4 vv = *(const float4*)(V + (size_t)(t0 + r) * 1024 + hb + c4 * 4);
            *(float4*)(&vs[r * 64 + c4 * 4]) = vv;
        }
        __syncthreads();

        float acc[4][4] = {};
        #pragma unroll 8
        for (int kk = 0; kk < 64; kk++) {
            float a[4], b[4];
            *(float4*)a = *(const float4*)(qsT + kk * 68 + ty * 4);
            *(float4*)b = *(const float4*)(ksT + kk * 68 + tx * 4);
            #pragma unroll
            for (int i = 0; i < 4; i++)
                #pragma unroll
                for (int jj = 0; jj < 4; jj++)
                    acc[i][jj] += a[i] * b[jj];
        }

        #pragma unroll
        for (int i = 0; i < 4; i++)
            #pragma unroll
            for (int jj = 0; jj < 4; jj++)
                acc[i][jj] = (acc[i][jj] + bc[i][jj] + bp[i][jj]) * inv_scale;

        #pragma unroll
        for (int i = 0; i < 4; i++) {
            float mt = fmaxf(fmaxf(acc[i][0], acc[i][1]), fmaxf(acc[i][2], acc[i][3]));
            mt = rmax16(mt);
            float mn = fmaxf(m_run[i], mt);
            float corr = __expf(m_run[i] - mn);
            m_run[i] = mn;
            float ls = 0.f;
            #pragma unroll
            for (int jj = 0; jj < 4; jj++) {
                acc[i][jj] = __expf(acc[i][jj] - mn);
                ls += acc[i][jj];
            }
            ls = rsum16(ls);
            l_run[i] = l_run[i] * corr + ls;
            #pragma unroll
            for (int jj = 0; jj < 4; jj++) o[i][jj] *= corr;
        }

        #pragma unroll
        for (int jj = 0; jj < 4; jj++) {
            float4 s4;
            s4.x = acc[0][jj]; s4.y = acc[1][jj]; s4.z = acc[2][jj]; s4.w = acc[3][jj];
            *(float4*)(ssT + (tx * 4 + jj) * 68 + ty * 4) = s4;
        }
        __syncthreads();

        #pragma unroll 8
        for (int j = 0; j < 64; j++) {
            float p[4], vv[4];
            *(float4*)p  = *(const float4*)(ssT + j * 68 + ty * 4);
            *(float4*)vv = *(const float4*)(vs + j * 64 + tx * 4);
            #pragma unroll
            for (int i = 0; i < 4; i++)
                #pragma unroll
                for (int jj = 0; jj < 4; jj++)
                    o[i][jj] += p[i] * vv[jj];
        }
        __syncthreads();
    }

    #pragma unroll
    for (int i = 0; i < 4; i++) {
        float invl = 1.f / l_run[i];
        float4 ov;
        ov.x = o[i][0] * invl; ov.y = o[i][1] * invl;
        ov.z = o[i][2] * invl; ov.w = o[i][3] * invl;
        *(float4*)(out + (size_t)(s0 + ty * 4 + i) * 1024 + hb + tx * 4) = ov;
    }
}

// ================= host launcher =================
extern "C" void kernel_launch(void* const* d_in, const int* in_sizes, int n_in,
                              void* d_out, int out_size)
{
    const float* hidden = (const float*)d_in[0];
    const float* rel    = (const float*)d_in[1];
    const float* Wq     = (const float*)d_in[2];
    const float* bq     = (const float*)d_in[3];
    const float* Wk     = (const float*)d_in[4];
    const float* bk     = (const float*)d_in[5];
    const float* Wv     = (const float*)d_in[6];
    const float* bv     = (const float*)d_in[7];
    const int*   ids    = (const int*)d_in[8];
    const int*   ids_t  = (const int*)d_in[9];
    float* out = (float*)d_out;

    void *pq, *pk, *pv, *ppk, *ppq, *pc2p, *pp2c;
    cudaGetSymbolAddress(&pq, g_q);
    cudaGetSymbolAddress(&pk, g_k);
    cudaGetSymbolAddress(&pv, g_v);
    cudaGetSymbolAddress(&ppk, g_pk);
    cudaGetSymbolAddress(&ppq, g_pq);
    cudaGetSymbolAddress(&pc2p, g_c2p_h);
    cudaGetSymbolAddress(&pp2c, g_p2c_h);
    float* q = (float*)pq;  float* k = (float*)pk;  float* v = (float*)pv;
    float* posk = (float*)ppk; float* posq = (float*)ppq;
    __half* c2p = (__half*)pc2p; __half* p2c = (__half*)pp2c;

    static int smem_set = 0;
    if (!smem_set) {
        cudaFuncSetAttribute(attn2, cudaFuncAttributeMaxDynamicSharedMemorySize,
                             ATT_SMEM_FLOATS * 4);
        smem_set = 1;
    }

    // QKV projections (tf32 tensor cores)
    dim3 gq(1024 / 128, S_LEN / 128, 3);
    gemm_proj_tc<<<gq, 256>>>(hidden, Wq, Wk, Wv, bq, bk, bv, q, k, v);

    // positional projections
    dim3 gp(1024 / 128, POSLEN / 128, 2);
    gemm_proj_tc<<<gp, 256>>>(rel, Wk, Wq, Wq, bk, bq, bq, posk, posq, posq);

    // c2p[h] = q_h @ posk_h^T ; p2c[h] = k_h @ posq_h^T  (tf32 tensor cores)
    dim3 gc(POSLEN / 128, S_LEN / 128, NHEAD);
    gemm_rel_tc<<<gc, 256>>>(q, posk, c2p, S_LEN, POSLEN);
    gemm_rel_tc<<<gc, 256>>>(k, posq, p2c, S_LEN, POSLEN);

    // fused attention (round-6 known-good)
    dim3 ga(S_LEN / 64, NHEAD);
    attn2<<<ga, 256, ATT_SMEM_FLOATS * 4>>>(q, k, v, c2p, p2c, ids, ids_t, out);
}

// round 13
// speedup vs baseline: 2.6147x; 1.1492x over previous
#include <cuda_runtime.h>
#include <cuda_fp16.h>
#include <math.h>
#include <stdint.h>

#define S_LEN 2048
#define D_DIM 1024
#define NHEAD 16
#define DH 64
#define POSLEN 512
#define C2P_ELEMS (NHEAD * S_LEN * POSLEN)

__device__ float g_q[S_LEN * D_DIM];
__device__ float g_k[S_LEN * D_DIM];
__device__ float g_v[S_LEN * D_DIM];
__device__ float g_pk[POSLEN * D_DIM];
__device__ float g_pq[POSLEN * D_DIM];
__device__ __half g_c2p_h[C2P_ELEMS];
__device__ __half g_p2c_h[C2P_ELEMS];
__device__ uint32_t g_kT[NHEAD * DH * S_LEN];   // per-head transposed K, tf32
__device__ __half   g_vT[NHEAD * DH * S_LEN];   // per-head transposed V, fp16

// ---------------- helpers ----------------
__device__ __forceinline__ uint32_t f2tf32(float f) {
    uint32_t r;
    asm("cvt.rna.tf32.f32 %0, %1;" : "=r"(r) : "f"(f));
    return r;
}
__device__ __forceinline__ void mma_tf32(
    float& d0, float& d1, float& d2, float& d3,
    uint32_t a0, uint32_t a1, uint32_t a2, uint32_t a3,
    uint32_t b0, uint32_t b1)
{
    asm("mma.sync.aligned.m16n8k8.row.col.f32.tf32.tf32.f32 "
        "{%0,%1,%2,%3}, {%4,%5,%6,%7}, {%8,%9}, {%0,%1,%2,%3};"
        : "+f"(d0), "+f"(d1), "+f"(d2), "+f"(d3)
        : "r"(a0), "r"(a1), "r"(a2), "r"(a3), "r"(b0), "r"(b1));
}
__device__ __forceinline__ void mma_f16(
    float& d0, float& d1, float& d2, float& d3,
    uint32_t a0, uint32_t a1, uint32_t a2, uint32_t a3,
    uint32_t b0, uint32_t b1)
{
    asm("mma.sync.aligned.m16n8k16.row.col.f32.f16.f16.f32 "
        "{%0,%1,%2,%3}, {%4,%5,%6,%7}, {%8,%9}, {%0,%1,%2,%3};"
        : "+f"(d0), "+f"(d1), "+f"(d2), "+f"(d3)
        : "r"(a0), "r"(a1), "r"(a2), "r"(a3), "r"(b0), "r"(b1));
}
__device__ __forceinline__ uint4 cvt4(float4 v) {
    uint4 r;
    r.x = f2tf32(v.x); r.y = f2tf32(v.y); r.z = f2tf32(v.z); r.w = f2tf32(v.w);
    return r;
}
__device__ __forceinline__ float fexp2(float x) {
    float r; asm("ex2.approx.ftz.f32 %0, %1;" : "=f"(r) : "f"(x)); return r;
}
__device__ __forceinline__ uint32_t packh2(float lo, float hi) {
    __half2 h = __floats2half2_rn(lo, hi);
    return *(uint32_t*)&h;
}

// ================= tf32 tensor-core projection GEMM (round-12, unchanged) =================
__global__ __launch_bounds__(256) void gemm_proj_tc(
    const float* __restrict__ A,
    const float* __restrict__ W0, const float* __restrict__ W1, const float* __restrict__ W2,
    const float* __restrict__ b0, const float* __restrict__ b1, const float* __restrict__ b2,
    float* __restrict__ C0, float* __restrict__ C1, float* __restrict__ C2)
{
    const float* W; const float* bias; float* C;
    if (blockIdx.z == 0)      { W = W0; bias = b0; C = C0; }
    else if (blockIdx.z == 1) { W = W1; bias = b1; C = C1; }
    else                      { W = W2; bias = b2; C = C2; }

    __shared__ uint32_t As[128 * 36];
    __shared__ uint32_t Bs[32 * 136];

    const int tid = threadIdx.x;
    const int w = tid >> 5, lane = tid & 31;
    const int g = lane >> 2, tg = lane & 3;
    const int wm = (w >> 2) * 64, wn = (w & 3) * 32;
    const int m0 = blockIdx.y * 128, n0 = blockIdx.x * 128;

    float d[4][4][4] = {};

    for (int k0 = 0; k0 < 1024; k0 += 32) {
        #pragma unroll
        for (int u = 0; u < 4; u++) {
            int idx = tid + u * 256;
            int r = idx >> 3, c4 = idx & 7;
            float4 av = *(const float4*)(A + (size_t)(m0 + r) * 1024 + k0 + c4 * 4);
            *(uint4*)(As + r * 36 + c4 * 4) = cvt4(av);
        }
        #pragma unroll
        for (int u = 0; u < 4; u++) {
            int idx = tid + u * 256;
            int r = idx >> 5, c4 = idx & 31;
            float4 bv = *(const float4*)(W + (size_t)(k0 + r) * 1024 + n0 + c4 * 4);
            *(uint4*)(Bs + r * 136 + c4 * 4) = cvt4(bv);
        }
        __syncthreads();

        #pragma unroll
        for (int ks = 0; ks < 4; ks++) {
            uint32_t af[4][4];
            #pragma unroll
            for (int mt = 0; mt < 4; mt++) {
                int row = wm + mt * 16 + g;
                af[mt][0] = As[row * 36 + ks * 8 + tg];
                af[mt][1] = As[(row + 8) * 36 + ks * 8 + tg];
                af[mt][2] = As[row * 36 + ks * 8 + tg + 4];
                af[mt][3] = As[(row + 8) * 36 + ks * 8 + tg + 4];
            }
            uint32_t bf[4][2];
            #pragma unroll
            for (int nt = 0; nt < 4; nt++) {
                int col = wn + nt * 8 + g;
                bf[nt][0] = Bs[(ks * 8 + tg) * 136 + col];
                bf[nt][1] = Bs[(ks * 8 + tg + 4) * 136 + col];
            }
            #pragma unroll
            for (int mt = 0; mt < 4; mt++)
                #pragma unroll
                for (int nt = 0; nt < 4; nt++)
                    mma_tf32(d[mt][nt][0], d[mt][nt][1], d[mt][nt][2], d[mt][nt][3],
                             af[mt][0], af[mt][1], af[mt][2], af[mt][3],
                             bf[nt][0], bf[nt][1]);
        }
        __syncthreads();
    }

    #pragma unroll
    for (int mt = 0; mt < 4; mt++) {
        int row = m0 + wm + mt * 16 + g;
        #pragma unroll
        for (int nt = 0; nt < 4; nt++) {
            int col = n0 + wn + nt * 8 + tg * 2;
            float bb0 = bias[col], bb1 = bias[col + 1];
            float2 v0 = make_float2(d[mt][nt][0] + bb0, d[mt][nt][1] + bb1);
            float2 v1 = make_float2(d[mt][nt][2] + bb0, d[mt][nt][3] + bb1);
            *(float2*)(C + (size_t)row * 1024 + col)       = v0;
            *(float2*)(C + (size_t)(row + 8) * 1024 + col) = v1;
        }
    }
}

// ================= tf32 tensor-core per-head NT GEMM -> fp16 table (round-12) =================
__global__ __launch_bounds__(256) void gemm_rel_tc(
    const float* __restrict__ A, const float* __restrict__ B, __half* __restrict__ C,
    int M, int N)
{
    __shared__ uint32_t As[128 * 36];
    __shared__ uint32_t Bs[128 * 36];

    const int tid = threadIdx.x;
    const int w = tid >> 5, lane = tid & 31;
    const int g = lane >> 2, tg = lane & 3;
    const int wm = (w >> 2) * 64, wn = (w & 3) * 32;
    const int h = blockIdx.z;
    const int hb = h * DH;
    const int m0 = blockIdx.y * 128, n0 = blockIdx.x * 128;

    float d[4][4][4] = {};

    for (int k0 = 0; k0 < 64; k0 += 32) {
        #pragma unroll
        for (int u = 0; u < 4; u++) {
            int idx = tid + u * 256;
            int r = idx >> 3, c4 = idx & 7;
            float4 av = *(const float4*)(A + (size_t)(m0 + r) * 1024 + hb + k0 + c4 * 4);
            *(uint4*)(As + r * 36 + c4 * 4) = cvt4(av);
        }
        #pragma unroll
        for (int u = 0; u < 4; u++) {
            int idx = tid + u * 256;
            int r = idx >> 3, c4 = idx & 7;
            float4 bv = *(const float4*)(B + (size_t)(n0 + r) * 1024 + hb + k0 + c4 * 4);
            *(uint4*)(Bs + r * 36 + c4 * 4) = cvt4(bv);
        }
        __syncthreads();

        #pragma unroll
        for (int ks = 0; ks < 4; ks++) {
            uint32_t af[4][4];
            #pragma unroll
            for (int mt = 0; mt < 4; mt++) {
                int row = wm + mt * 16 + g;
                af[mt][0] = As[row * 36 + ks * 8 + tg];
                af[mt][1] = As[(row + 8) * 36 + ks * 8 + tg];
                af[mt][2] = As[row * 36 + ks * 8 + tg + 4];
                af[mt][3] = As[(row + 8) * 36 + ks * 8 + tg + 4];
            }
            uint32_t bf[4][2];
            #pragma unroll
            for (int nt = 0; nt < 4; nt++) {
                int col = wn + nt * 8 + g;
                bf[nt][0] = Bs[col * 36 + ks * 8 + tg];
                bf[nt][1] = Bs[col * 36 + ks * 8 + tg + 4];
            }
            #pragma unroll
            for (int mt = 0; mt < 4; mt++)
                #pragma unroll
                for (int nt = 0; nt < 4; nt++)
                    mma_tf32(d[mt][nt][0], d[mt][nt][1], d[mt][nt][2], d[mt][nt][3],
                             af[mt][0], af[mt][1], af[mt][2], af[mt][3],
                             bf[nt][0], bf[nt][1]);
        }
        __syncthreads();
    }

    __half* Ch = C + (size_t)h * M * N;
    #pragma unroll
    for (int mt = 0; mt < 4; mt++) {
        int row = m0 + wm + mt * 16 + g;
        #pragma unroll
        for (int nt = 0; nt < 4; nt++) {
            int col = n0 + wn + nt * 8 + tg * 2;
            *(__half2*)(Ch + (size_t)row * N + col) =
                __floats2half2_rn(d[mt][nt][0], d[mt][nt][1]);
            *(__half2*)(Ch + (size_t)(row + 8) * N + col) =
                __floats2half2_rn(d[mt][nt][2], d[mt][nt][3]);
        }
    }
}

// ================= prep: transpose K (tf32) and V (fp16) to per-head [d][t] =================
__global__ __launch_bounds__(256) void prep_kv(
    const float* __restrict__ K, const float* __restrict__ V,
    uint32_t* __restrict__ kT, __half* __restrict__ vT)
{
    __shared__ float ksm[64][68];
    __shared__ float vsm[64][68];
    const int h = blockIdx.y;
    const int t0 = blockIdx.x * 64;
    const int tid = threadIdx.x;

    #pragma unroll
    for (int u = 0; u < 4; u++) {
        int idx = tid + u * 256;
        int r = idx >> 4, c4 = idx & 15;
        *(float4*)&ksm[r][c4 * 4] = *(const float4*)(K + (size_t)(t0 + r) * 1024 + h * 64 + c4 * 4);
        *(float4*)&vsm[r][c4 * 4] = *(const float4*)(V + (size_t)(t0 + r) * 1024 + h * 64 + c4 * 4);
    }
    __syncthreads();

    // kT rows (d) of tf32 along t
    #pragma unroll
    for (int u = 0; u < 4; u++) {
        int idx = tid + u * 256;
        int d = idx >> 4, c4 = idx & 15;
        uint4 o;
        o.x = f2tf32(ksm[c4 * 4 + 0][d]);
        o.y = f2tf32(ksm[c4 * 4 + 1][d]);
        o.z = f2tf32(ksm[c4 * 4 + 2][d]);
        o.w = f2tf32(ksm[c4 * 4 + 3][d]);
        *(uint4*)(kT + (size_t)(h * 64 + d) * 2048 + t0 + c4 * 4) = o;
    }
    // vT rows (d) of fp16 along t
    #pragma unroll
    for (int u = 0; u < 2; u++) {
        int idx = tid + u * 256;
        int d = idx >> 3, c8 = idx & 7;
        __half2 hh[4];
        #pragma unroll
        for (int p = 0; p < 4; p++)
            hh[p] = __floats2half2_rn(vsm[c8 * 8 + 2 * p][d], vsm[c8 * 8 + 2 * p + 1][d]);
        *(uint4*)(vT + (size_t)(h * 64 + d) * 2048 + t0 + c8 * 8) = *(uint4*)hh;
    }
}

// ================= fused flash attention, tensor-core fragments =================
// 128 threads = 4 warps; warp owns m16 q-rows; K tile 64/iter.
#define KST 72   // ks_s stride (uint32 words)
#define VST 72   // vs_s stride (halfs)
#define BST 68   // bias stride (halfs)

__global__ __launch_bounds__(128, 3) void attn3(
    const float* __restrict__ Q, const uint32_t* __restrict__ kT,
    const __half* __restrict__ vT, const __half* __restrict__ c2p,
    const __half* __restrict__ p2c, const int* __restrict__ ids,
    const int* __restrict__ ids_t, float* __restrict__ out)
{
    __shared__ uint32_t ks_s[64 * KST];   // K tile [d][t] tf32 (also Q staging in prologue)
    __shared__ __half  vs_s[64 * VST];    // V tile [d][t] fp16
    __shared__ __half  bc_s[64 * BST];    // c2p bias [s][t]
    __shared__ __half  bp_s[64 * BST];    // p2c bias [t][s]

    const int h  = blockIdx.y;
    const int s0 = blockIdx.x * 64;
    const int hb = h * DH;
    const int tid = threadIdx.x;
    const int w = tid >> 5, lane = tid & 31;
    const int g = lane >> 2, tg = lane & 3;
    const int wm = w * 16;

    const float SC = 0.07216878364870322f * 1.4426950408889634f;  // inv_scale * log2e

    // ---- prologue: stage Q tile into ks_s (as floats), build tf32 A-fragments ----
    {
        float* qs = (float*)ks_s;
        #pragma unroll
        for (int u = 0; u < 8; u++) {
            int idx = tid + u * 128;
            int r = idx >> 4, c4 = idx & 15;
            *(float4*)&qs[r * KST + c4 * 4] =
                *(const float4*)(Q + (size_t)(s0 + r) * 1024 + hb + c4 * 4);
        }
    }
    __syncthreads();
    uint32_t qa[8][4];
    {
        const float* qs = (const float*)ks_s;
        #pragma unroll
        for (int ks = 0; ks < 8; ks++) {
            qa[ks][0] = f2tf32(qs[(wm + g) * KST + ks * 8 + tg]);
            qa[ks][1] = f2tf32(qs[(wm + g + 8) * KST + ks * 8 + tg]);
            qa[ks][2] = f2tf32(qs[(wm + g) * KST + ks * 8 + tg + 4]);
            qa[ks][3] = f2tf32(qs[(wm + g + 8) * KST + ks * 8 + tg + 4]);
        }
    }

    float o[8][4] = {};
    float m0r = -INFINITY, m1r = -INFINITY, l0r = 0.f, l1r = 0.f;

    for (int t0 = 0; t0 < S_LEN; t0 += 64) {
        __syncthreads();   // buffers free (prev iter consumers done)

        // ---- cooperative tile loads ----
        #pragma unroll
        for (int u = 0; u < 8; u++) {            // K tile: 64 d-rows x 16 uint4
            int idx = tid + u * 128;
            int d = idx >> 4, c4 = idx & 15;
            *(uint4*)&ks_s[d * KST + c4 * 4] =
                *(const uint4*)(kT + (size_t)(h * 64 + d) * 2048 + t0 + c4 * 4);
        }
        #pragma unroll
        for (int u = 0; u < 4; u++) {            // V tile: 64 d-rows x 8 uint4 (halfs)
            int idx = tid + u * 128;
            int d = idx >> 3, c8 = idx & 7;
            *(uint4*)&vs_s[d * VST + c8 * 8] =
                *(const uint4*)(vT + (size_t)(h * 64 + d) * 2048 + t0 + c8 * 8);
        }
        // c2p bias staging: [s][t]
        #pragma unroll
        for (int u = 0; u < 8; u++) {
            int idx = tid + u * 128;
            int r = idx >> 4, c4 = idx & 15;
            int4 iv = *(const int4*)(ids + ((size_t)(h * S_LEN + s0 + r) << 11) + t0 + c4 * 4);
            __half hv[4];
            hv[0] = c2p[iv.x]; hv[1] = c2p[iv.y]; hv[2] = c2p[iv.z]; hv[3] = c2p[iv.w];
            *(uint2*)&bc_s[r * BST + c4 * 4] = *(uint2*)hv;
        }
        // p2c bias staging: [t][s]
        #pragma unroll
        for (int u = 0; u < 8; u++) {
            int idx = tid + u * 128;
            int r = idx >> 4, c4 = idx & 15;
            int4 iv = *(const int4*)(ids_t + ((size_t)(h * S_LEN + t0 + r) << 11) + s0 + c4 * 4);
            __half hv[4];
            hv[0] = p2c[iv.x]; hv[1] = p2c[iv.y]; hv[2] = p2c[iv.z]; hv[3] = p2c[iv.w];
            *(uint2*)&bp_s[r * BST + c4 * 4] = *(uint2*)hv;
        }
        __syncthreads();

        // ---- QK^T via tf32 mma: m16 x n64 per warp ----
        float dq[8][4] = {};
        #pragma unroll
        for (int ks = 0; ks < 8; ks++) {
            #pragma unroll
            for (int nt = 0; nt < 8; nt++) {
                uint32_t b0 = ks_s[(ks * 8 + tg) * KST + nt * 8 + g];
                uint32_t b1 = ks_s[(ks * 8 + tg + 4) * KST + nt * 8 + g];
                mma_tf32(dq[nt][0], dq[nt][1], dq[nt][2], dq[nt][3],
                         qa[ks][0], qa[ks][1], qa[ks][2], qa[ks][3], b0, b1);
            }
        }

        // ---- bias fixup + scale (log2 domain) ----
        #pragma unroll
        for (int nt = 0; nt < 8; nt++) {
            int c = nt * 8 + 2 * tg;
            __half2 bc0 = *(__half2*)&bc_s[(wm + g) * BST + c];
            __half2 bc1 = *(__half2*)&bc_s[(wm + g + 8) * BST + c];
            float bp0 = __half2float(bp_s[(c + 0) * BST + wm + g]);
            float bp1 = __half2float(bp_s[(c + 1) * BST + wm + g]);
            float bp2 = __half2float(bp_s[(c + 0) * BST + wm + g + 8]);
            float bp3 = __half2float(bp_s[(c + 1) * BST + wm + g + 8]);
            dq[nt][0] = (dq[nt][0] + __low2float(bc0)  + bp0) * SC;
            dq[nt][1] = (dq[nt][1] + __high2float(bc0) + bp1) * SC;
            dq[nt][2] = (dq[nt][2] + __low2float(bc1)  + bp2) * SC;
            dq[nt][3] = (dq[nt][3] + __high2float(bc1) + bp3) * SC;
        }

        // ---- online softmax on fragments (quad shuffles) ----
        float mt0 = -INFINITY, mt1 = -INFINITY;
        #pragma unroll
        for (int nt = 0; nt < 8; nt++) {
            mt0 = fmaxf(mt0, fmaxf(dq[nt][0], dq[nt][1]));
            mt1 = fmaxf(mt1, fmaxf(dq[nt][2], dq[nt][3]));
        }
        mt0 = fmaxf(mt0, __shfl_xor_sync(0xffffffffu, mt0, 1));
        mt0 = fmaxf(mt0, __shfl_xor_sync(0xffffffffu, mt0, 2));
        mt1 = fmaxf(mt1, __shfl_xor_sync(0xffffffffu, mt1, 1));
        mt1 = fmaxf(mt1, __shfl_xor_sync(0xffffffffu, mt1, 2));
        float mn0 = fmaxf(m0r, mt0), mn1 = fmaxf(m1r, mt1);
        float c0 = fexp2(m0r - mn0), c1 = fexp2(m1r - mn1);
        m0r = mn0; m1r = mn1;
        float ls0 = 0.f, ls1 = 0.f;
        #pragma unroll
        for (int nt = 0; nt < 8; nt++) {
            dq[nt][0] = fexp2(dq[nt][0] - mn0);
            dq[nt][1] = fexp2(dq[nt][1] - mn0);
            dq[nt][2] = fexp2(dq[nt][2] - mn1);
            dq[nt][3] = fexp2(dq[nt][3] - mn1);
            ls0 += dq[nt][0] + dq[nt][1];
            ls1 += dq[nt][2] + dq[nt][3];
        }
        ls0 += __shfl_xor_sync(0xffffffffu, ls0, 1);
        ls0 += __shfl_xor_sync(0xffffffffu, ls0, 2);
        ls1 += __shfl_xor_sync(0xffffffffu, ls1, 1);
        ls1 += __shfl_xor_sync(0xffffffffu, ls1, 2);
        l0r = l0r * c0 + ls0;
        l1r = l1r * c1 + ls1;
        #pragma unroll
        for (int nt = 0; nt < 8; nt++) {
            o[nt][0] *= c0; o[nt][1] *= c0; o[nt][2] *= c1; o[nt][3] *= c1;
        }

        // ---- P (fp16 fragments, direct repack) @ V via fp16 mma ----
        #pragma unroll
        for (int kt = 0; kt < 4; kt++) {
            uint32_t a0 = packh2(dq[2 * kt][0], dq[2 * kt][1]);
            uint32_t a1 = packh2(dq[2 * kt][2], dq[2 * kt][3]);
            uint32_t a2 = packh2(dq[2 * kt + 1][0], dq[2 * kt + 1][1]);
            uint32_t a3 = packh2(dq[2 * kt + 1][2], dq[2 * kt + 1][3]);
            #pragma unroll
            for (int nt = 0; nt < 8; nt++) {
                uint32_t b0 = *(uint32_t*)&vs_s[(nt * 8 + g) * VST + kt * 16 + 2 * tg];
                uint32_t b1 = *(uint32_t*)&vs_s[(nt * 8 + g) * VST + kt * 16 + 8 + 2 * tg];
                mma_f16(o[nt][0], o[nt][1], o[nt][2], o[nt][3], a0, a1, a2, a3, b0, b1);
            }
        }
    }

    // ---- epilogue ----
    float i0 = 1.f / l0r, i1 = 1.f / l1r;
    #pragma unroll
    for (int nt = 0; nt < 8; nt++) {
        int c = hb + nt * 8 + 2 * tg;
        *(float2*)(out + (size_t)(s0 + wm + g) * 1024 + c) =
            make_float2(o[nt][0] * i0, o[nt][1] * i0);
        *(float2*)(out + (size_t)(s0 + wm + g + 8) * 1024 + c) =
            make_float2(o[nt][2] * i1, o[nt][3] * i1);
    }
}

// ================= host launcher =================
extern "C" void kernel_launch(void* const* d_in, const int* in_sizes, int n_in,
                              void* d_out, int out_size)
{
    const float* hidden = (const float*)d_in[0];
    const float* rel    = (const float*)d_in[1];
    const float* Wq     = (const float*)d_in[2];
    const float* bq     = (const float*)d_in[3];
    const float* Wk     = (const float*)d_in[4];
    const float* bk     = (const float*)d_in[5];
    const float* Wv     = (const float*)d_in[6];
    const float* bv     = (const float*)d_in[7];
    const int*   ids    = (const int*)d_in[8];
    const int*   ids_t  = (const int*)d_in[9];
    float* out = (float*)d_out;

    void *pq, *pk, *pv, *ppk, *ppq, *pc2p, *pp2c, *pkT, *pvT;
    cudaGetSymbolAddress(&pq, g_q);
    cudaGetSymbolAddress(&pk, g_k);
    cudaGetSymbolAddress(&pv, g_v);
    cudaGetSymbolAddress(&ppk, g_pk);
    cudaGetSymbolAddress(&ppq, g_pq);
    cudaGetSymbolAddress(&pc2p, g_c2p_h);
    cudaGetSymbolAddress(&pp2c, g_p2c_h);
    cudaGetSymbolAddress(&pkT, g_kT);
    cudaGetSymbolAddress(&pvT, g_vT);
    float* q = (float*)pq;  float* k = (float*)pk;  float* v = (float*)pv;
    float* posk = (float*)ppk; float* posq = (float*)ppq;
    __half* c2p = (__half*)pc2p; __half* p2c = (__half*)pp2c;
    uint32_t* kT = (uint32_t*)pkT; __half* vT = (__half*)pvT;

    // QKV projections (tf32 TC)
    dim3 gq(1024 / 128, S_LEN / 128, 3);
    gemm_proj_tc<<<gq, 256>>>(hidden, Wq, Wk, Wv, bq, bk, bv, q, k, v);

    // transpose K/V per head for the attention kernel
    dim3 gt(S_LEN / 64, NHEAD);
    prep_kv<<<gt, 256>>>(k, v, kT, vT);

    // positional projections
    dim3 gp(1024 / 128, POSLEN / 128, 2);
    gemm_proj_tc<<<gp, 256>>>(rel, Wk, Wq, Wq, bk, bq, bq, posk, posq, posq);

    // relative-score tables (tf32 TC -> fp16)
    dim3 gc(POSLEN / 128, S_LEN / 128, NHEAD);
    gemm_rel_tc<<<gc, 256>>>(q, posk, c2p, S_LEN, POSLEN);
    gemm_rel_tc<<<gc, 256>>>(k, posq, p2c, S_LEN, POSLEN);

    // fused attention (tensor-core fragments)
    dim3 ga(S_LEN / 64, NHEAD);
    attn3<<<ga, 128>>>(q, kT, vT, c2p, p2c, ids, ids_t, out);
}

// round 16
// speedup vs baseline: 3.0449x; 1.1645x over previous
#include <cuda_runtime.h>
#include <cuda_fp16.h>
#include <math.h>
#include <stdint.h>

#define S_LEN 2048
#define D_DIM 1024
#define NHEAD 16
#define DH 64
#define POSLEN 512
#define C2P_ELEMS (NHEAD * S_LEN * POSLEN)

__device__ float g_q[S_LEN * D_DIM];
__device__ float g_k[S_LEN * D_DIM];
__device__ float g_v[S_LEN * D_DIM];
__device__ float g_pk[POSLEN * D_DIM];
__device__ float g_pq[POSLEN * D_DIM];
__device__ __half g_c2p_h[C2P_ELEMS];
__device__ __half g_p2c_h[C2P_ELEMS];
__device__ uint32_t g_kT[NHEAD * DH * S_LEN];   // per-head transposed K, tf32
__device__ __half   g_vT[NHEAD * DH * S_LEN];   // per-head transposed V, fp16

// ---------------- helpers ----------------
__device__ __forceinline__ uint32_t f2tf32(float f) {
    uint32_t r;
    asm("cvt.rna.tf32.f32 %0, %1;" : "=r"(r) : "f"(f));
    return r;
}
__device__ __forceinline__ void mma_tf32(
    float& d0, float& d1, float& d2, float& d3,
    uint32_t a0, uint32_t a1, uint32_t a2, uint32_t a3,
    uint32_t b0, uint32_t b1)
{
    asm("mma.sync.aligned.m16n8k8.row.col.f32.tf32.tf32.f32 "
        "{%0,%1,%2,%3}, {%4,%5,%6,%7}, {%8,%9}, {%0,%1,%2,%3};"
        : "+f"(d0), "+f"(d1), "+f"(d2), "+f"(d3)
        : "r"(a0), "r"(a1), "r"(a2), "r"(a3), "r"(b0), "r"(b1));
}
__device__ __forceinline__ void mma_f16(
    float& d0, float& d1, float& d2, float& d3,
    uint32_t a0, uint32_t a1, uint32_t a2, uint32_t a3,
    uint32_t b0, uint32_t b1)
{
    asm("mma.sync.aligned.m16n8k16.row.col.f32.f16.f16.f32 "
        "{%0,%1,%2,%3}, {%4,%5,%6,%7}, {%8,%9}, {%0,%1,%2,%3};"
        : "+f"(d0), "+f"(d1), "+f"(d2), "+f"(d3)
        : "r"(a0), "r"(a1), "r"(a2), "r"(a3), "r"(b0), "r"(b1));
}
__device__ __forceinline__ uint4 cvt4(float4 v) {
    uint4 r;
    r.x = f2tf32(v.x); r.y = f2tf32(v.y); r.z = f2tf32(v.z); r.w = f2tf32(v.w);
    return r;
}
__device__ __forceinline__ float fexp2(float x) {
    float r; asm("ex2.approx.ftz.f32 %0, %1;" : "=f"(r) : "f"(x)); return r;
}
__device__ __forceinline__ uint32_t packh2(float lo, float hi) {
    __half2 h = __floats2half2_rn(lo, hi);
    return *(uint32_t*)&h;
}

// ================= tf32 tensor-core projection GEMM =================
__global__ __launch_bounds__(256) void gemm_proj_tc(
    const float* __restrict__ A,
    const float* __restrict__ W0, const float* __restrict__ W1, const float* __restrict__ W2,
    const float* __restrict__ b0, const float* __restrict__ b1, const float* __restrict__ b2,
    float* __restrict__ C0, float* __restrict__ C1, float* __restrict__ C2)
{
    const float* W; const float* bias; float* C;
    if (blockIdx.z == 0)      { W = W0; bias = b0; C = C0; }
    else if (blockIdx.z == 1) { W = W1; bias = b1; C = C1; }
    else                      { W = W2; bias = b2; C = C2; }

    __shared__ uint32_t As[128 * 36];
    __shared__ uint32_t Bs[32 * 136];

    const int tid = threadIdx.x;
    const int w = tid >> 5, lane = tid & 31;
    const int g = lane >> 2, tg = lane & 3;
    const int wm = (w >> 2) * 64, wn = (w & 3) * 32;
    const int m0 = blockIdx.y * 128, n0 = blockIdx.x * 128;

    float d[4][4][4] = {};

    for (int k0 = 0; k0 < 1024; k0 += 32) {
        #pragma unroll
        for (int u = 0; u < 4; u++) {
            int idx = tid + u * 256;
            int r = idx >> 3, c4 = idx & 7;
            float4 av = *(const float4*)(A + (size_t)(m0 + r) * 1024 + k0 + c4 * 4);
            *(uint4*)(As + r * 36 + c4 * 4) = cvt4(av);
        }
        #pragma unroll
        for (int u = 0; u < 4; u++) {
            int idx = tid + u * 256;
            int r = idx >> 5, c4 = idx & 31;
            float4 bv = *(const float4*)(W + (size_t)(k0 + r) * 1024 + n0 + c4 * 4);
            *(uint4*)(Bs + r * 136 + c4 * 4) = cvt4(bv);
        }
        __syncthreads();

        #pragma unroll
        for (int ks = 0; ks < 4; ks++) {
            uint32_t af[4][4];
            #pragma unroll
            for (int mt = 0; mt < 4; mt++) {
                int row = wm + mt * 16 + g;
                af[mt][0] = As[row * 36 + ks * 8 + tg];
                af[mt][1] = As[(row + 8) * 36 + ks * 8 + tg];
                af[mt][2] = As[row * 36 + ks * 8 + tg + 4];
                af[mt][3] = As[(row + 8) * 36 + ks * 8 + tg + 4];
            }
            uint32_t bf[4][2];
            #pragma unroll
            for (int nt = 0; nt < 4; nt++) {
                int col = wn + nt * 8 + g;
                bf[nt][0] = Bs[(ks * 8 + tg) * 136 + col];
                bf[nt][1] = Bs[(ks * 8 + tg + 4) * 136 + col];
            }
            #pragma unroll
            for (int mt = 0; mt < 4; mt++)
                #pragma unroll
                for (int nt = 0; nt < 4; nt++)
                    mma_tf32(d[mt][nt][0], d[mt][nt][1], d[mt][nt][2], d[mt][nt][3],
                             af[mt][0], af[mt][1], af[mt][2], af[mt][3],
                             bf[nt][0], bf[nt][1]);
        }
        __syncthreads();
    }

    #pragma unroll
    for (int mt = 0; mt < 4; mt++) {
        int row = m0 + wm + mt * 16 + g;
        #pragma unroll
        for (int nt = 0; nt < 4; nt++) {
            int col = n0 + wn + nt * 8 + tg * 2;
            float bb0 = bias[col], bb1 = bias[col + 1];
            float2 v0 = make_float2(d[mt][nt][0] + bb0, d[mt][nt][1] + bb1);
            float2 v1 = make_float2(d[mt][nt][2] + bb0, d[mt][nt][3] + bb1);
            *(float2*)(C + (size_t)row * 1024 + col)       = v0;
            *(float2*)(C + (size_t)(row + 8) * 1024 + col) = v1;
        }
    }
}

// ================= tf32 tensor-core per-head NT GEMM -> fp16 table =================
__global__ __launch_bounds__(256) void gemm_rel_tc(
    const float* __restrict__ A, const float* __restrict__ B, __half* __restrict__ C,
    int M, int N)
{
    __shared__ uint32_t As[128 * 36];
    __shared__ uint32_t Bs[128 * 36];

    const int tid = threadIdx.x;
    const int w = tid >> 5, lane = tid & 31;
    const int g = lane >> 2, tg = lane & 3;
    const int wm = (w >> 2) * 64, wn = (w & 3) * 32;
    const int h = blockIdx.z;
    const int hb = h * DH;
    const int m0 = blockIdx.y * 128, n0 = blockIdx.x * 128;

    float d[4][4][4] = {};

    for (int k0 = 0; k0 < 64; k0 += 32) {
        #pragma unroll
        for (int u = 0; u < 4; u++) {
            int idx = tid + u * 256;
            int r = idx >> 3, c4 = idx & 7;
            float4 av = *(const float4*)(A + (size_t)(m0 + r) * 1024 + hb + k0 + c4 * 4);
            *(uint4*)(As + r * 36 + c4 * 4) = cvt4(av);
        }
        #pragma unroll
        for (int u = 0; u < 4; u++) {
            int idx = tid + u * 256;
            int r = idx >> 3, c4 = idx & 7;
            float4 bv = *(const float4*)(B + (size_t)(n0 + r) * 1024 + hb + k0 + c4 * 4);
            *(uint4*)(Bs + r * 36 + c4 * 4) = cvt4(bv);
        }
        __syncthreads();

        #pragma unroll
        for (int ks = 0; ks < 4; ks++) {
            uint32_t af[4][4];
            #pragma unroll
            for (int mt = 0; mt < 4; mt++) {
                int row = wm + mt * 16 + g;
                af[mt][0] = As[row * 36 + ks * 8 + tg];
                af[mt][1] = As[(row + 8) * 36 + ks * 8 + tg];
                af[mt][2] = As[row * 36 + ks * 8 + tg + 4];
                af[mt][3] = As[(row + 8) * 36 + ks * 8 + tg + 4];
            }
            uint32_t bf[4][2];
            #pragma unroll
            for (int nt = 0; nt < 4; nt++) {
                int col = wn + nt * 8 + g;
                bf[nt][0] = Bs[col * 36 + ks * 8 + tg];
                bf[nt][1] = Bs[col * 36 + ks * 8 + tg + 4];
            }
            #pragma unroll
            for (int mt = 0; mt < 4; mt++)
                #pragma unroll
                for (int nt = 0; nt < 4; nt++)
                    mma_tf32(d[mt][nt][0], d[mt][nt][1], d[mt][nt][2], d[mt][nt][3],
                             af[mt][0], af[mt][1], af[mt][2], af[mt][3],
                             bf[nt][0], bf[nt][1]);
        }
        __syncthreads();
    }

    __half* Ch = C + (size_t)h * M * N;
    #pragma unroll
    for (int mt = 0; mt < 4; mt++) {
        int row = m0 + wm + mt * 16 + g;
        #pragma unroll
        for (int nt = 0; nt < 4; nt++) {
            int col = n0 + wn + nt * 8 + tg * 2;
            *(__half2*)(Ch + (size_t)row * N + col) =
                __floats2half2_rn(d[mt][nt][0], d[mt][nt][1]);
            *(__half2*)(Ch + (size_t)(row + 8) * N + col) =
                __floats2half2_rn(d[mt][nt][2], d[mt][nt][3]);
        }
    }
}

// ================= prep: transpose K (tf32) and V (fp16) to per-head [d][t] =================
__global__ __launch_bounds__(256) void prep_kv(
    const float* __restrict__ K, const float* __restrict__ V,
    uint32_t* __restrict__ kT, __half* __restrict__ vT)
{
    __shared__ float ksm[64][68];
    __shared__ float vsm[64][68];
    const int h = blockIdx.y;
    const int t0 = blockIdx.x * 64;
    const int tid = threadIdx.x;

    #pragma unroll
    for (int u = 0; u < 4; u++) {
        int idx = tid + u * 256;
        int r = idx >> 4, c4 = idx & 15;
        *(float4*)&ksm[r][c4 * 4] = *(const float4*)(K + (size_t)(t0 + r) * 1024 + h * 64 + c4 * 4);
        *(float4*)&vsm[r][c4 * 4] = *(const float4*)(V + (size_t)(t0 + r) * 1024 + h * 64 + c4 * 4);
    }
    __syncthreads();

    #pragma unroll
    for (int u = 0; u < 4; u++) {
        int idx = tid + u * 256;
        int d = idx >> 4, c4 = idx & 15;
        uint4 o;
        o.x = f2tf32(ksm[c4 * 4 + 0][d]);
        o.y = f2tf32(ksm[c4 * 4 + 1][d]);
        o.z = f2tf32(ksm[c4 * 4 + 2][d]);
        o.w = f2tf32(ksm[c4 * 4 + 3][d]);
        *(uint4*)(kT + (size_t)(h * 64 + d) * 2048 + t0 + c4 * 4) = o;
    }
    #pragma unroll
    for (int u = 0; u < 2; u++) {
        int idx = tid + u * 256;
        int d = idx >> 3, c8 = idx & 7;
        __half2 hh[4];
        #pragma unroll
        for (int p = 0; p < 4; p++)
            hh[p] = __floats2half2_rn(vsm[c8 * 8 + 2 * p][d], vsm[c8 * 8 + 2 * p + 1][d]);
        *(uint4*)(vT + (size_t)(h * 64 + d) * 2048 + t0 + c8 * 8) = *(uint4*)hh;
    }
}

// ================= fused flash attention, fragment-direct bias =================
#define KST 72
#define VST 72

__global__ __launch_bounds__(128, 3) void attn4(
    const float* __restrict__ Q, const uint32_t* __restrict__ kT,
    const __half* __restrict__ vT, const __half* __restrict__ c2p,
    const __half* __restrict__ p2c, const int* __restrict__ ids,
    const int* __restrict__ ids_t, float* __restrict__ out)
{
    __shared__ uint32_t ks_s[64 * KST];   // K tile [d][t] tf32 (Q staging in prologue)
    __shared__ __half  vs_s[64 * VST];    // V tile [d][t] fp16

    const int h  = blockIdx.y;
    const int s0 = blockIdx.x * 64;
    const int hb = h * DH;
    const int tid = threadIdx.x;
    const int w = tid >> 5, lane = tid & 31;
    const int g = lane >> 2, tg = lane & 3;
    const int wm = w * 16;

    const float SC = 0.07216878364870322f * 1.4426950408889634f;  // inv_scale * log2e

    // ---- prologue: stage Q tile into ks_s, build tf32 A-fragments ----
    {
        float* qs = (float*)ks_s;
        #pragma unroll
        for (int u = 0; u < 8; u++) {
            int idx = tid + u * 128;
            int r = idx >> 4, c4 = idx & 15;
            *(float4*)&qs[r * KST + c4 * 4] =
                *(const float4*)(Q + (size_t)(s0 + r) * 1024 + hb + c4 * 4);
        }
    }
    __syncthreads();
    uint32_t qa[8][4];
    {
        const float* qs = (const float*)ks_s;
        #pragma unroll
        for (int ks = 0; ks < 8; ks++) {
            qa[ks][0] = f2tf32(qs[(wm + g) * KST + ks * 8 + tg]);
            qa[ks][1] = f2tf32(qs[(wm + g + 8) * KST + ks * 8 + tg]);
            qa[ks][2] = f2tf32(qs[(wm + g) * KST + ks * 8 + tg + 4]);
            qa[ks][3] = f2tf32(qs[(wm + g + 8) * KST + ks * 8 + tg + 4]);
        }
    }

    // per-thread fragment-coordinate index bases
    const int* idr0_base = ids + (((size_t)h * S_LEN + s0 + wm + g) << 11) + 2 * tg;
    const int* idr1_base = idr0_base + ((size_t)8 << 11);
    const int* idt_base  = ids_t + (((size_t)h * S_LEN + 2 * tg) << 11) + s0 + wm + g;

    float o[8][4] = {};
    float m0r = -INFINITY, m1r = -INFINITY, l0r = 0.f, l1r = 0.f;

    for (int t0 = 0; t0 < S_LEN; t0 += 64) {
        __syncthreads();   // previous consumers done

        // ---- K/V tile staging (issue LDG early) ----
        #pragma unroll
        for (int u = 0; u < 8; u++) {
            int idx = tid + u * 128;
            int d = idx >> 4, c4 = idx & 15;
            *(uint4*)&ks_s[d * KST + c4 * 4] =
                *(const uint4*)(kT + (size_t)(h * 64 + d) * 2048 + t0 + c4 * 4);
        }
        #pragma unroll
        for (int u = 0; u < 4; u++) {
            int idx = tid + u * 128;
            int d = idx >> 3, c8 = idx & 7;
            *(uint4*)&vs_s[d * VST + c8 * 8] =
                *(const uint4*)(vT + (size_t)(h * 64 + d) * 2048 + t0 + c8 * 8);
        }

        // ---- fragment-direct bias: idx loads + gathers, accumulated into dq ----
        float dq[8][4];
        #pragma unroll
        for (int half = 0; half < 2; half++) {
            int2 ic0[4], ic1[4];
            int ip[4][4];
            #pragma unroll
            for (int q4 = 0; q4 < 4; q4++) {
                int nt = half * 4 + q4;
                ic0[q4] = *(const int2*)(idr0_base + t0 + nt * 8);
                ic1[q4] = *(const int2*)(idr1_base + t0 + nt * 8);
                const int* tb = idt_base + ((size_t)(t0 + nt * 8) << 11);
                ip[q4][0] = tb[0];
                ip[q4][1] = tb[(size_t)1 << 11];
                ip[q4][2] = tb[8];
                ip[q4][3] = tb[((size_t)1 << 11) + 8];
            }
            #pragma unroll
            for (int q4 = 0; q4 < 4; q4++) {
                int nt = half * 4 + q4;
                dq[nt][0] = __half2float(c2p[ic0[q4].x]) + __half2float(p2c[ip[q4][0]]);
                dq[nt][1] = __half2float(c2p[ic0[q4].y]) + __half2float(p2c[ip[q4][1]]);
                dq[nt][2] = __half2float(c2p[ic1[q4].x]) + __half2float(p2c[ip[q4][2]]);
                dq[nt][3] = __half2float(c2p[ic1[q4].y]) + __half2float(p2c[ip[q4][3]]);
            }
        }
        __syncthreads();

        // ---- QK^T via tf32 mma (accumulates on top of bias) ----
        #pragma unroll
        for (int ks = 0; ks < 8; ks++) {
            #pragma unroll
            for (int nt = 0; nt < 8; nt++) {
                uint32_t b0 = ks_s[(ks * 8 + tg) * KST + nt * 8 + g];
                uint32_t b1 = ks_s[(ks * 8 + tg + 4) * KST + nt * 8 + g];
                mma_tf32(dq[nt][0], dq[nt][1], dq[nt][2], dq[nt][3],
                         qa[ks][0], qa[ks][1], qa[ks][2], qa[ks][3], b0, b1);
            }
        }
        #pragma unroll
        for (int nt = 0; nt < 8; nt++) {
            dq[nt][0] *= SC; dq[nt][1] *= SC; dq[nt][2] *= SC; dq[nt][3] *= SC;
        }

        // ---- online softmax on fragments ----
        float mt0 = -INFINITY, mt1 = -INFINITY;
        #pragma unroll
        for (int nt = 0; nt < 8; nt++) {
            mt0 = fmaxf(mt0, fmaxf(dq[nt][0], dq[nt][1]));
            mt1 = fmaxf(mt1, fmaxf(dq[nt][2], dq[nt][3]));
        }
        mt0 = fmaxf(mt0, __shfl_xor_sync(0xffffffffu, mt0, 1));
        mt0 = fmaxf(mt0, __shfl_xor_sync(0xffffffffu, mt0, 2));
        mt1 = fmaxf(mt1, __shfl_xor_sync(0xffffffffu, mt1, 1));
        mt1 = fmaxf(mt1, __shfl_xor_sync(0xffffffffu, mt1, 2));
        float mn0 = fmaxf(m0r, mt0), mn1 = fmaxf(m1r, mt1);
        float c0 = fexp2(m0r - mn0), c1 = fexp2(m1r - mn1);
        m0r = mn0; m1r = mn1;
        float ls0 = 0.f, ls1 = 0.f;
        #pragma unroll
        for (int nt = 0; nt < 8; nt++) {
            dq[nt][0] = fexp2(dq[nt][0] - mn0);
            dq[nt][1] = fexp2(dq[nt][1] - mn0);
            dq[nt][2] = fexp2(dq[nt][2] - mn1);
            dq[nt][3] = fexp2(dq[nt][3] - mn1);
            ls0 += dq[nt][0] + dq[nt][1];
            ls1 += dq[nt][2] + dq[nt][3];
        }
        ls0 += __shfl_xor_sync(0xffffffffu, ls0, 1);
        ls0 += __shfl_xor_sync(0xffffffffu, ls0, 2);
        ls1 += __shfl_xor_sync(0xffffffffu, ls1, 1);
        ls1 += __shfl_xor_sync(0xffffffffu, ls1, 2);
        l0r = l0r * c0 + ls0;
        l1r = l1r * c1 + ls1;
        #pragma unroll
        for (int nt = 0; nt < 8; nt++) {
            o[nt][0] *= c0; o[nt][1] *= c0; o[nt][2] *= c1; o[nt][3] *= c1;
        }

        // ---- P (fp16 fragments, direct repack) @ V via fp16 mma ----
        #pragma unroll
        for (int kt = 0; kt < 4; kt++) {
            uint32_t a0 = packh2(dq[2 * kt][0], dq[2 * kt][1]);
            uint32_t a1 = packh2(dq[2 * kt][2], dq[2 * kt][3]);
            uint32_t a2 = packh2(dq[2 * kt + 1][0], dq[2 * kt + 1][1]);
            uint32_t a3 = packh2(dq[2 * kt + 1][2], dq[2 * kt + 1][3]);
            #pragma unroll
            for (int nt = 0; nt < 8; nt++) {
                uint32_t b0 = *(uint32_t*)&vs_s[(nt * 8 + g) * VST + kt * 16 + 2 * tg];
                uint32_t b1 = *(uint32_t*)&vs_s[(nt * 8 + g) * VST + kt * 16 + 8 + 2 * tg];
                mma_f16(o[nt][0], o[nt][1], o[nt][2], o[nt][3], a0, a1, a2, a3, b0, b1);
            }
        }
    }

    // ---- epilogue ----
    float i0 = 1.f / l0r, i1 = 1.f / l1r;
    #pragma unroll
    for (int nt = 0; nt < 8; nt++) {
        int c = hb + nt * 8 + 2 * tg;
        *(float2*)(out + (size_t)(s0 + wm + g) * 1024 + c) =
            make_float2(o[nt][0] * i0, o[nt][1] * i0);
        *(float2*)(out + (size_t)(s0 + wm + g + 8) * 1024 + c) =
            make_float2(o[nt][2] * i1, o[nt][3] * i1);
    }
}

// ================= host launcher =================
extern "C" void kernel_launch(void* const* d_in, const int* in_sizes, int n_in,
                              void* d_out, int out_size)
{
    const float* hidden = (const float*)d_in[0];
    const float* rel    = (const float*)d_in[1];
    const float* Wq     = (const float*)d_in[2];
    const float* bq     = (const float*)d_in[3];
    const float* Wk     = (const float*)d_in[4];
    const float* bk     = (const float*)d_in[5];
    const float* Wv     = (const float*)d_in[6];
    const float* bv     = (const float*)d_in[7];
    const int*   ids    = (const int*)d_in[8];
    const int*   ids_t  = (const int*)d_in[9];
    float* out = (float*)d_out;

    void *pq, *pk, *pv, *ppk, *ppq, *pc2p, *pp2c, *pkT, *pvT;
    cudaGetSymbolAddress(&pq, g_q);
    cudaGetSymbolAddress(&pk, g_k);
    cudaGetSymbolAddress(&pv, g_v);
    cudaGetSymbolAddress(&ppk, g_pk);
    cudaGetSymbolAddress(&ppq, g_pq);
    cudaGetSymbolAddress(&pc2p, g_c2p_h);
    cudaGetSymbolAddress(&pp2c, g_p2c_h);
    cudaGetSymbolAddress(&pkT, g_kT);
    cudaGetSymbolAddress(&pvT, g_vT);
    float* q = (float*)pq;  float* k = (float*)pk;  float* v = (float*)pv;
    float* posk = (float*)ppk; float* posq = (float*)ppq;
    __half* c2p = (__half*)pc2p; __half* p2c = (__half*)pp2c;
    uint32_t* kT = (uint32_t*)pkT; __half* vT = (__half*)pvT;

    // QKV projections (tf32 TC)
    dim3 gq(1024 / 128, S_LEN / 128, 3);
    gemm_proj_tc<<<gq, 256>>>(hidden, Wq, Wk, Wv, bq, bk, bv, q, k, v);

    // transpose K/V per head
    dim3 gt(S_LEN / 64, NHEAD);
    prep_kv<<<gt, 256>>>(k, v, kT, vT);

    // positional projections
    dim3 gp(1024 / 128, POSLEN / 128, 2);
    gemm_proj_tc<<<gp, 256>>>(rel, Wk, Wq, Wq, bk, bq, bq, posk, posq, posq);

    // relative-score tables
    dim3 gc(POSLEN / 128, S_LEN / 128, NHEAD);
    gemm_rel_tc<<<gc, 256>>>(q, posk, c2p, S_LEN, POSLEN);
    gemm_rel_tc<<<gc, 256>>>(k, posq, p2c, S_LEN, POSLEN);

    // fused attention (fragment-direct bias)
    dim3 ga(S_LEN / 64, NHEAD);
    attn4<<<ga, 128>>>(q, kT, vT, c2p, p2c, ids, ids_t, out);
}

// round 17
// speedup vs baseline: 3.5797x; 1.1756x over previous
#include <cuda_runtime.h>
#include <cuda_fp16.h>
#include <math.h>
#include <stdint.h>

#define S_LEN 2048
#define D_DIM 1024
#define NHEAD 16
#define DH 64
#define POSLEN 512
#define C2P_ELEMS (NHEAD * S_LEN * POSLEN)

__device__ float g_q[S_LEN * D_DIM];
__device__ float g_k[S_LEN * D_DIM];
__device__ float g_v[S_LEN * D_DIM];
__device__ float g_pk[POSLEN * D_DIM];
__device__ float g_pq[POSLEN * D_DIM];
__device__ __half g_c2p_h[C2P_ELEMS];
__device__ __half g_p2c_h[C2P_ELEMS];
__device__ uint32_t g_kT[NHEAD * DH * S_LEN];   // per-head transposed K, tf32
__device__ __half   g_vT[NHEAD * DH * S_LEN];   // per-head transposed V, fp16

// ---------------- helpers ----------------
__device__ __forceinline__ uint32_t f2tf32(float f) {
    uint32_t r;
    asm("cvt.rna.tf32.f32 %0, %1;" : "=r"(r) : "f"(f));
    return r;
}
__device__ __forceinline__ void mma_tf32(
    float& d0, float& d1, float& d2, float& d3,
    uint32_t a0, uint32_t a1, uint32_t a2, uint32_t a3,
    uint32_t b0, uint32_t b1)
{
    asm("mma.sync.aligned.m16n8k8.row.col.f32.tf32.tf32.f32 "
        "{%0,%1,%2,%3}, {%4,%5,%6,%7}, {%8,%9}, {%0,%1,%2,%3};"
        : "+f"(d0), "+f"(d1), "+f"(d2), "+f"(d3)
        : "r"(a0), "r"(a1), "r"(a2), "r"(a3), "r"(b0), "r"(b1));
}
__device__ __forceinline__ void mma_f16(
    float& d0, float& d1, float& d2, float& d3,
    uint32_t a0, uint32_t a1, uint32_t a2, uint32_t a3,
    uint32_t b0, uint32_t b1)
{
    asm("mma.sync.aligned.m16n8k16.row.col.f32.f16.f16.f32 "
        "{%0,%1,%2,%3}, {%4,%5,%6,%7}, {%8,%9}, {%0,%1,%2,%3};"
        : "+f"(d0), "+f"(d1), "+f"(d2), "+f"(d3)
        : "r"(a0), "r"(a1), "r"(a2), "r"(a3), "r"(b0), "r"(b1));
}
__device__ __forceinline__ uint4 cvt4(float4 v) {
    uint4 r;
    r.x = f2tf32(v.x); r.y = f2tf32(v.y); r.z = f2tf32(v.z); r.w = f2tf32(v.w);
    return r;
}
__device__ __forceinline__ float fexp2(float x) {
    float r; asm("ex2.approx.ftz.f32 %0, %1;" : "=f"(r) : "f"(x)); return r;
}
__device__ __forceinline__ uint32_t packh2(float lo, float hi) {
    __half2 h = __floats2half2_rn(lo, hi);
    return *(uint32_t*)&h;
}
__device__ __forceinline__ void cp_async16(uint32_t dst, const void* src) {
    asm volatile("cp.async.cg.shared.global [%0], [%1], 16;" :: "r"(dst), "l"(src));
}
__device__ __forceinline__ void cp_commit() {
    asm volatile("cp.async.commit_group;");
}
__device__ __forceinline__ void cp_wait0() {
    asm volatile("cp.async.wait_group 0;");
}

// ================= tf32 tensor-core projection GEMM =================
__global__ __launch_bounds__(256) void gemm_proj_tc(
    const float* __restrict__ A,
    const float* __restrict__ W0, const float* __restrict__ W1, const float* __restrict__ W2,
    const float* __restrict__ b0, const float* __restrict__ b1, const float* __restrict__ b2,
    float* __restrict__ C0, float* __restrict__ C1, float* __restrict__ C2)
{
    const float* W; const float* bias; float* C;
    if (blockIdx.z == 0)      { W = W0; bias = b0; C = C0; }
    else if (blockIdx.z == 1) { W = W1; bias = b1; C = C1; }
    else                      { W = W2; bias = b2; C = C2; }

    __shared__ uint32_t As[128 * 36];
    __shared__ uint32_t Bs[32 * 136];

    const int tid = threadIdx.x;
    const int w = tid >> 5, lane = tid & 31;
    const int g = lane >> 2, tg = lane & 3;
    const int wm = (w >> 2) * 64, wn = (w & 3) * 32;
    const int m0 = blockIdx.y * 128, n0 = blockIdx.x * 128;

    float d[4][4][4] = {};

    for (int k0 = 0; k0 < 1024; k0 += 32) {
        #pragma unroll
        for (int u = 0; u < 4; u++) {
            int idx = tid + u * 256;
            int r = idx >> 3, c4 = idx & 7;
            float4 av = *(const float4*)(A + (size_t)(m0 + r) * 1024 + k0 + c4 * 4);
            *(uint4*)(As + r * 36 + c4 * 4) = cvt4(av);
        }
        #pragma unroll
        for (int u = 0; u < 4; u++) {
            int idx = tid + u * 256;
            int r = idx >> 5, c4 = idx & 31;
            float4 bv = *(const float4*)(W + (size_t)(k0 + r) * 1024 + n0 + c4 * 4);
            *(uint4*)(Bs + r * 136 + c4 * 4) = cvt4(bv);
        }
        __syncthreads();

        #pragma unroll
        for (int ks = 0; ks < 4; ks++) {
            uint32_t af[4][4];
            #pragma unroll
            for (int mt = 0; mt < 4; mt++) {
                int row = wm + mt * 16 + g;
                af[mt][0] = As[row * 36 + ks * 8 + tg];
                af[mt][1] = As[(row + 8) * 36 + ks * 8 + tg];
                af[mt][2] = As[row * 36 + ks * 8 + tg + 4];
                af[mt][3] = As[(row + 8) * 36 + ks * 8 + tg + 4];
            }
            uint32_t bf[4][2];
            #pragma unroll
            for (int nt = 0; nt < 4; nt++) {
                int col = wn + nt * 8 + g;
                bf[nt][0] = Bs[(ks * 8 + tg) * 136 + col];
                bf[nt][1] = Bs[(ks * 8 + tg + 4) * 136 + col];
            }
            #pragma unroll
            for (int mt = 0; mt < 4; mt++)
                #pragma unroll
                for (int nt = 0; nt < 4; nt++)
                    mma_tf32(d[mt][nt][0], d[mt][nt][1], d[mt][nt][2], d[mt][nt][3],
                             af[mt][0], af[mt][1], af[mt][2], af[mt][3],
                             bf[nt][0], bf[nt][1]);
        }
        __syncthreads();
    }

    #pragma unroll
    for (int mt = 0; mt < 4; mt++) {
        int row = m0 + wm + mt * 16 + g;
        #pragma unroll
        for (int nt = 0; nt < 4; nt++) {
            int col = n0 + wn + nt * 8 + tg * 2;
            float bb0 = bias[col], bb1 = bias[col + 1];
            float2 v0 = make_float2(d[mt][nt][0] + bb0, d[mt][nt][1] + bb1);
            float2 v1 = make_float2(d[mt][nt][2] + bb0, d[mt][nt][3] + bb1);
            *(float2*)(C + (size_t)row * 1024 + col)       = v0;
            *(float2*)(C + (size_t)(row + 8) * 1024 + col) = v1;
        }
    }
}

// ================= tf32 tensor-core per-head NT GEMM -> fp16 table =================
__global__ __launch_bounds__(256) void gemm_rel_tc(
    const float* __restrict__ A, const float* __restrict__ B, __half* __restrict__ C,
    int M, int N)
{
    __shared__ uint32_t As[128 * 36];
    __shared__ uint32_t Bs[128 * 36];

    const int tid = threadIdx.x;
    const int w = tid >> 5, lane = tid & 31;
    const int g = lane >> 2, tg = lane & 3;
    const int wm = (w >> 2) * 64, wn = (w & 3) * 32;
    const int h = blockIdx.z;
    const int hb = h * DH;
    const int m0 = blockIdx.y * 128, n0 = blockIdx.x * 128;

    float d[4][4][4] = {};

    for (int k0 = 0; k0 < 64; k0 += 32) {
        #pragma unroll
        for (int u = 0; u < 4; u++) {
            int idx = tid + u * 256;
            int r = idx >> 3, c4 = idx & 7;
            float4 av = *(const float4*)(A + (size_t)(m0 + r) * 1024 + hb + k0 + c4 * 4);
            *(uint4*)(As + r * 36 + c4 * 4) = cvt4(av);
        }
        #pragma unroll
        for (int u = 0; u < 4; u++) {
            int idx = tid + u * 256;
            int r = idx >> 3, c4 = idx & 7;
            float4 bv = *(const float4*)(B + (size_t)(n0 + r) * 1024 + hb + k0 + c4 * 4);
            *(uint4*)(Bs + r * 36 + c4 * 4) = cvt4(bv);
        }
        __syncthreads();

        #pragma unroll
        for (int ks = 0; ks < 4; ks++) {
            uint32_t af[4][4];
            #pragma unroll
            for (int mt = 0; mt < 4; mt++) {
                int row = wm + mt * 16 + g;
                af[mt][0] = As[row * 36 + ks * 8 + tg];
                af[mt][1] = As[(row + 8) * 36 + ks * 8 + tg];
                af[mt][2] = As[row * 36 + ks * 8 + tg + 4];
                af[mt][3] = As[(row + 8) * 36 + ks * 8 + tg + 4];
            }
            uint32_t bf[4][2];
            #pragma unroll
            for (int nt = 0; nt < 4; nt++) {
                int col = wn + nt * 8 + g;
                bf[nt][0] = Bs[col * 36 + ks * 8 + tg];
                bf[nt][1] = Bs[col * 36 + ks * 8 + tg + 4];
            }
            #pragma unroll
            for (int mt = 0; mt < 4; mt++)
                #pragma unroll
                for (int nt = 0; nt < 4; nt++)
                    mma_tf32(d[mt][nt][0], d[mt][nt][1], d[mt][nt][2], d[mt][nt][3],
                             af[mt][0], af[mt][1], af[mt][2], af[mt][3],
                             bf[nt][0], bf[nt][1]);
        }
        __syncthreads();
    }

    __half* Ch = C + (size_t)h * M * N;
    #pragma unroll
    for (int mt = 0; mt < 4; mt++) {
        int row = m0 + wm + mt * 16 + g;
        #pragma unroll
        for (int nt = 0; nt < 4; nt++) {
            int col = n0 + wn + nt * 8 + tg * 2;
            *(__half2*)(Ch + (size_t)row * N + col) =
                __floats2half2_rn(d[mt][nt][0], d[mt][nt][1]);
            *(__half2*)(Ch + (size_t)(row + 8) * N + col) =
                __floats2half2_rn(d[mt][nt][2], d[mt][nt][3]);
        }
    }
}

// ================= prep: transpose K (tf32) and V (fp16) to per-head [d][t] =================
__global__ __launch_bounds__(256) void prep_kv(
    const float* __restrict__ K, const float* __restrict__ V,
    uint32_t* __restrict__ kT, __half* __restrict__ vT)
{
    __shared__ float ksm[64][68];
    __shared__ float vsm[64][68];
    const int h = blockIdx.y;
    const int t0 = blockIdx.x * 64;
    const int tid = threadIdx.x;

    #pragma unroll
    for (int u = 0; u < 4; u++) {
        int idx = tid + u * 256;
        int r = idx >> 4, c4 = idx & 15;
        *(float4*)&ksm[r][c4 * 4] = *(const float4*)(K + (size_t)(t0 + r) * 1024 + h * 64 + c4 * 4);
        *(float4*)&vsm[r][c4 * 4] = *(const float4*)(V + (size_t)(t0 + r) * 1024 + h * 64 + c4 * 4);
    }
    __syncthreads();

    #pragma unroll
    for (int u = 0; u < 4; u++) {
        int idx = tid + u * 256;
        int d = idx >> 4, c4 = idx & 15;
        uint4 o;
        o.x = f2tf32(ksm[c4 * 4 + 0][d]);
        o.y = f2tf32(ksm[c4 * 4 + 1][d]);
        o.z = f2tf32(ksm[c4 * 4 + 2][d]);
        o.w = f2tf32(ksm[c4 * 4 + 3][d]);
        *(uint4*)(kT + (size_t)(h * 64 + d) * 2048 + t0 + c4 * 4) = o;
    }
    #pragma unroll
    for (int u = 0; u < 2; u++) {
        int idx = tid + u * 256;
        int d = idx >> 3, c8 = idx & 7;
        __half2 hh[4];
        #pragma unroll
        for (int p = 0; p < 4; p++)
            hh[p] = __floats2half2_rn(vsm[c8 * 8 + 2 * p][d], vsm[c8 * 8 + 2 * p + 1][d]);
        *(uint4*)(vT + (size_t)(h * 64 + d) * 2048 + t0 + c8 * 8) = *(uint4*)hh;
    }
}

// ================= fused flash attention: pipelined gathers + cp.async K/V =================
#define KST 72
#define VST 72

__global__ __launch_bounds__(128, 2) void attn5(
    const float* __restrict__ Q, const uint32_t* __restrict__ kT,
    const __half* __restrict__ vT, const __half* __restrict__ c2p,
    const __half* __restrict__ p2c, const int* __restrict__ ids,
    const int* __restrict__ ids_t, float* __restrict__ out)
{
    __shared__ __align__(16) uint32_t ks_s[2][64 * KST];   // K tiles [d][t] tf32
    __shared__ __align__(16) __half  vs_s[2][64 * VST];    // V tiles [d][t] fp16

    const int h  = blockIdx.y;
    const int s0 = blockIdx.x * 64;
    const int hb = h * DH;
    const int tid = threadIdx.x;
    const int w = tid >> 5, lane = tid & 31;
    const int g = lane >> 2, tg = lane & 3;
    const int wm = w * 16;

    const float SC = 0.07216878364870322f * 1.4426950408889634f;  // inv_scale * log2e

    // staging coordinates for cp.async fills
    const int kd = tid >> 4, kc = (tid & 15);          // used with u-loop: d = kd + ... see below
    (void)kd; (void)kc;

    // ---- issue cp.async fill of buffer 0 (t=0) as early as possible ----
    {
        #pragma unroll
        for (int u = 0; u < 8; u++) {
            int idx = tid + u * 128;
            int d = idx >> 4, c4 = idx & 15;
            uint32_t dst = (uint32_t)__cvta_generic_to_shared(&ks_s[0][d * KST + c4 * 4]);
            cp_async16(dst, kT + (size_t)(h * 64 + d) * 2048 + 0 + c4 * 4);
        }
        #pragma unroll
        for (int u = 0; u < 4; u++) {
            int idx = tid + u * 128;
            int d = idx >> 3, c8 = idx & 7;
            uint32_t dst = (uint32_t)__cvta_generic_to_shared(&vs_s[0][d * VST + c8 * 8]);
            cp_async16(dst, vT + (size_t)(h * 64 + d) * 2048 + 0 + c8 * 8);
        }
        cp_commit();
    }

    // ---- stage Q tile into buffer 1 (floats), build tf32 A-fragments ----
    {
        float* qs = (float*)ks_s[1];
        #pragma unroll
        for (int u = 0; u < 8; u++) {
            int idx = tid + u * 128;
            int r = idx >> 4, c4 = idx & 15;
            *(float4*)&qs[r * KST + c4 * 4] =
                *(const float4*)(Q + (size_t)(s0 + r) * 1024 + hb + c4 * 4);
        }
    }
    __syncthreads();
    uint32_t qa[8][4];
    {
        const float* qs = (const float*)ks_s[1];
        #pragma unroll
        for (int ks = 0; ks < 8; ks++) {
            qa[ks][0] = f2tf32(qs[(wm + g) * KST + ks * 8 + tg]);
            qa[ks][1] = f2tf32(qs[(wm + g + 8) * KST + ks * 8 + tg]);
            qa[ks][2] = f2tf32(qs[(wm + g) * KST + ks * 8 + tg + 4]);
            qa[ks][3] = f2tf32(qs[(wm + g + 8) * KST + ks * 8 + tg + 4]);
        }
    }

    // per-thread fragment-coordinate index bases
    const int* idr0_base = ids + (((size_t)h * S_LEN + s0 + wm + g) << 11) + 2 * tg;
    const int* idr1_base = idr0_base + ((size_t)8 << 11);
    const int* idt_base  = ids_t + (((size_t)h * S_LEN + 2 * tg) << 11) + s0 + wm + g;

    // ---- prefetch indices for iteration 0 ----
    int2 ic0[8], ic1[8];
    int  ip[8][4];
    #pragma unroll
    for (int nt = 0; nt < 8; nt++) {
        ic0[nt] = *(const int2*)(idr0_base + nt * 8);
        ic1[nt] = *(const int2*)(idr1_base + nt * 8);
        const int* tb = idt_base + ((size_t)(nt * 8) << 11);
        ip[nt][0] = tb[0];
        ip[nt][1] = tb[(size_t)1 << 11];
        ip[nt][2] = tb[8];
        ip[nt][3] = tb[((size_t)1 << 11) + 8];
    }

    cp_wait0();
    __syncthreads();

    float o[8][4] = {};
    float m0r = -INFINITY, m1r = -INFINITY, l0r = 0.f, l1r = 0.f;

    for (int t0 = 0; t0 < S_LEN; t0 += 64) {
        const int cur = (t0 >> 6) & 1;
        const uint32_t* ksb = ks_s[cur];
        const __half*  vsb = vs_s[cur];
        const int tn = (t0 + 64 < S_LEN) ? t0 + 64 : t0;

        // ---- 1. prefetch next K/V tiles via cp.async into the other buffer ----
        #pragma unroll
        for (int u = 0; u < 8; u++) {
            int idx = tid + u * 128;
            int d = idx >> 4, c4 = idx & 15;
            uint32_t dst = (uint32_t)__cvta_generic_to_shared(&ks_s[cur ^ 1][d * KST + c4 * 4]);
            cp_async16(dst, kT + (size_t)(h * 64 + d) * 2048 + tn + c4 * 4);
        }
        #pragma unroll
        for (int u = 0; u < 4; u++) {
            int idx = tid + u * 128;
            int d = idx >> 3, c8 = idx & 7;
            uint32_t dst = (uint32_t)__cvta_generic_to_shared(&vs_s[cur ^ 1][d * VST + c8 * 8]);
            cp_async16(dst, vT + (size_t)(h * 64 + d) * 2048 + tn + c8 * 8);
        }
        cp_commit();

        // ---- 2. issue bias gathers (indices already in registers) ----
        __half gc[8][4], gp[8][4];
        #pragma unroll
        for (int nt = 0; nt < 8; nt++) {
            gc[nt][0] = c2p[ic0[nt].x];
            gc[nt][1] = c2p[ic0[nt].y];
            gc[nt][2] = c2p[ic1[nt].x];
            gc[nt][3] = c2p[ic1[nt].y];
            gp[nt][0] = p2c[ip[nt][0]];
            gp[nt][1] = p2c[ip[nt][1]];
            gp[nt][2] = p2c[ip[nt][2]];
            gp[nt][3] = p2c[ip[nt][3]];
        }

        // ---- 3. QK^T via tf32 mma (gathers resolve underneath) ----
        float dq[8][4] = {};
        #pragma unroll
        for (int ks = 0; ks < 8; ks++) {
            #pragma unroll
            for (int nt = 0; nt < 8; nt++) {
                uint32_t b0 = ksb[(ks * 8 + tg) * KST + nt * 8 + g];
                uint32_t b1 = ksb[(ks * 8 + tg + 4) * KST + nt * 8 + g];
                mma_tf32(dq[nt][0], dq[nt][1], dq[nt][2], dq[nt][3],
                         qa[ks][0], qa[ks][1], qa[ks][2], qa[ks][3], b0, b1);
            }
        }

        // ---- 4. fold bias + scale ----
        #pragma unroll
        for (int nt = 0; nt < 8; nt++) {
            dq[nt][0] = (dq[nt][0] + __half2float(gc[nt][0]) + __half2float(gp[nt][0])) * SC;
            dq[nt][1] = (dq[nt][1] + __half2float(gc[nt][1]) + __half2float(gp[nt][1])) * SC;
            dq[nt][2] = (dq[nt][2] + __half2float(gc[nt][2]) + __half2float(gp[nt][2])) * SC;
            dq[nt][3] = (dq[nt][3] + __half2float(gc[nt][3]) + __half2float(gp[nt][3])) * SC;
        }

        // ---- 5. prefetch indices for the next iteration (latency spans softmax+PV) ----
        #pragma unroll
        for (int nt = 0; nt < 8; nt++) {
            ic0[nt] = *(const int2*)(idr0_base + tn + nt * 8);
            ic1[nt] = *(const int2*)(idr1_base + tn + nt * 8);
            const int* tb = idt_base + ((size_t)(tn + nt * 8) << 11);
            ip[nt][0] = tb[0];
            ip[nt][1] = tb[(size_t)1 << 11];
            ip[nt][2] = tb[8];
            ip[nt][3] = tb[((size_t)1 << 11) + 8];
        }

        // ---- 6. online softmax on fragments ----
        float mt0 = -INFINITY, mt1 = -INFINITY;
        #pragma unroll
        for (int nt = 0; nt < 8; nt++) {
            mt0 = fmaxf(mt0, fmaxf(dq[nt][0], dq[nt][1]));
            mt1 = fmaxf(mt1, fmaxf(dq[nt][2], dq[nt][3]));
        }
        mt0 = fmaxf(mt0, __shfl_xor_sync(0xffffffffu, mt0, 1));
        mt0 = fmaxf(mt0, __shfl_xor_sync(0xffffffffu, mt0, 2));
        mt1 = fmaxf(mt1, __shfl_xor_sync(0xffffffffu, mt1, 1));
        mt1 = fmaxf(mt1, __shfl_xor_sync(0xffffffffu, mt1, 2));
        float mn0 = fmaxf(m0r, mt0), mn1 = fmaxf(m1r, mt1);
        float c0 = fexp2(m0r - mn0), c1 = fexp2(m1r - mn1);
        m0r = mn0; m1r = mn1;
        float ls0 = 0.f, ls1 = 0.f;
        #pragma unroll
        for (int nt = 0; nt < 8; nt++) {
            dq[nt][0] = fexp2(dq[nt][0] - mn0);
            dq[nt][1] = fexp2(dq[nt][1] - mn0);
            dq[nt][2] = fexp2(dq[nt][2] - mn1);
            dq[nt][3] = fexp2(dq[nt][3] - mn1);
            ls0 += dq[nt][0] + dq[nt][1];
            ls1 += dq[nt][2] + dq[nt][3];
        }
        ls0 += __shfl_xor_sync(0xffffffffu, ls0, 1);
        ls0 += __shfl_xor_sync(0xffffffffu, ls0, 2);
        ls1 += __shfl_xor_sync(0xffffffffu, ls1, 1);
        ls1 += __shfl_xor_sync(0xffffffffu, ls1, 2);
        l0r = l0r * c0 + ls0;
        l1r = l1r * c1 + ls1;
        #pragma unroll
        for (int nt = 0; nt < 8; nt++) {
            o[nt][0] *= c0; o[nt][1] *= c0; o[nt][2] *= c1; o[nt][3] *= c1;
        }

        // ---- 7. P (fp16 fragments) @ V via fp16 mma ----
        #pragma unroll
        for (int kt = 0; kt < 4; kt++) {
            uint32_t a0 = packh2(dq[2 * kt][0], dq[2 * kt][1]);
            uint32_t a1 = packh2(dq[2 * kt][2], dq[2 * kt][3]);
            uint32_t a2 = packh2(dq[2 * kt + 1][0], dq[2 * kt + 1][1]);
            uint32_t a3 = packh2(dq[2 * kt + 1][2], dq[2 * kt + 1][3]);
            #pragma unroll
            for (int nt = 0; nt < 8; nt++) {
                uint32_t b0 = *(uint32_t*)&vsb[(nt * 8 + g) * VST + kt * 16 + 2 * tg];
                uint32_t b1 = *(uint32_t*)&vsb[(nt * 8 + g) * VST + kt * 16 + 8 + 2 * tg];
                mma_f16(o[nt][0], o[nt][1], o[nt][2], o[nt][3], a0, a1, a2, a3, b0, b1);
            }
        }

        // ---- 8. next tile ready? ----
        cp_wait0();
        __syncthreads();
    }

    // ---- epilogue ----
    float i0 = 1.f / l0r, i1 = 1.f / l1r;
    #pragma unroll
    for (int nt = 0; nt < 8; nt++) {
        int c = hb + nt * 8 + 2 * tg;
        *(float2*)(out + (size_t)(s0 + wm + g) * 1024 + c) =
            make_float2(o[nt][0] * i0, o[nt][1] * i0);
        *(float2*)(out + (size_t)(s0 + wm + g + 8) * 1024 + c) =
            make_float2(o[nt][2] * i1, o[nt][3] * i1);
    }
}

// ================= host launcher =================
extern "C" void kernel_launch(void* const* d_in, const int* in_sizes, int n_in,
                              void* d_out, int out_size)
{
    const float* hidden = (const float*)d_in[0];
    const float* rel    = (const float*)d_in[1];
    const float* Wq     = (const float*)d_in[2];
    const float* bq     = (const float*)d_in[3];
    const float* Wk     = (const float*)d_in[4];
    const float* bk     = (const float*)d_in[5];
    const float* Wv     = (const float*)d_in[6];
    const float* bv     = (const float*)d_in[7];
    const int*   ids    = (const int*)d_in[8];
    const int*   ids_t  = (const int*)d_in[9];
    float* out = (float*)d_out;

    void *pq, *pk, *pv, *ppk, *ppq, *pc2p, *pp2c, *pkT, *pvT;
    cudaGetSymbolAddress(&pq, g_q);
    cudaGetSymbolAddress(&pk, g_k);
    cudaGetSymbolAddress(&pv, g_v);
    cudaGetSymbolAddress(&ppk, g_pk);
    cudaGetSymbolAddress(&ppq, g_pq);
    cudaGetSymbolAddress(&pc2p, g_c2p_h);
    cudaGetSymbolAddress(&pp2c, g_p2c_h);
    cudaGetSymbolAddress(&pkT, g_kT);
    cudaGetSymbolAddress(&pvT, g_vT);
    float* q = (float*)pq;  float* k = (float*)pk;  float* v = (float*)pv;
    float* posk = (float*)ppk; float* posq = (float*)ppq;
    __half* c2p = (__half*)pc2p; __half* p2c = (__half*)pp2c;
    uint32_t* kT = (uint32_t*)pkT; __half* vT = (__half*)pvT;

    // QKV projections (tf32 TC)
    dim3 gq(1024 / 128, S_LEN / 128, 3);
    gemm_proj_tc<<<gq, 256>>>(hidden, Wq, Wk, Wv, bq, bk, bv, q, k, v);

    // transpose K/V per head
    dim3 gt(S_LEN / 64, NHEAD);
    prep_kv<<<gt, 256>>>(k, v, kT, vT);

    // positional projections
    dim3 gp(1024 / 128, POSLEN / 128, 2);
    gemm_proj_tc<<<gp, 256>>>(rel, Wk, Wq, Wq, bk, bq, bq, posk, posq, posq);

    // relative-score tables
    dim3 gc(POSLEN / 128, S_LEN / 128, NHEAD);
    gemm_rel_tc<<<gc, 256>>>(q, posk, c2p, S_LEN, POSLEN);
    gemm_rel_tc<<<gc, 256>>>(k, posq, p2c, S_LEN, POSLEN);

    // fused attention (pipelined gathers + cp.async double buffer)
    dim3 ga(S_LEN / 64, NHEAD);
    attn5<<<ga, 128>>>(q, kT, vT, c2p, p2c, ids, ids_t, out);
}